// round 5
// baseline (speedup 1.0000x reference)
#include <cuda_runtime.h>
#include <cuda_fp16.h>
#include <cstdint>

// Problem constants
#define BATCH_SEQ 640          // B*S = 32*20
#define THREADS   512
#define ADJ_THR   0.05f

typedef unsigned long long ull;

// ---- packed f32x2 helpers ----
__device__ __forceinline__ void fma2(ull& d, ull a, ull b) {
    asm("fma.rn.f32x2 %0, %1, %2, %0;" : "+l"(d) : "l"(a), "l"(b));
}
__device__ __forceinline__ ull pack2(float x, float y) {
    ull r; asm("mov.b64 %0, {%1, %2};" : "=l"(r) : "f"(x), "f"(y)); return r;
}
__device__ __forceinline__ float2 unpack2(ull v) {
    float2 f; asm("mov.b64 {%0, %1}, %2;" : "=f"(f.x), "=f"(f.y) : "l"(v)); return f;
}
__device__ __forceinline__ float rcp_approx(float x) {
    float r; asm("rcp.approx.f32 %0, %1;" : "=f"(r) : "f"(x)); return r;
}
// e^y for y in [0,1]: degree-7 Taylor (max rel err ~2.8e-5)
__device__ __forceinline__ float exp01(float y) {
    float p = 1.9841270e-4f;
    p = fmaf(p, y, 1.3888889e-3f);
    p = fmaf(p, y, 8.3333333e-3f);
    p = fmaf(p, y, 4.1666668e-2f);
    p = fmaf(p, y, 1.6666667e-1f);
    p = fmaf(p, y, 0.5f);
    p = fmaf(p, y, 1.0f);
    p = fmaf(p, y, 1.0f);
    return p;
}
// fp16 mma m16n8k16, fp32 accum
__device__ __forceinline__ void mma_f16(float c[4],
                                        uint32_t a0, uint32_t a1, uint32_t a2, uint32_t a3,
                                        uint32_t b0, uint32_t b1) {
    asm volatile("mma.sync.aligned.m16n8k16.row.col.f32.f16.f16.f32 "
                 "{%0,%1,%2,%3}, {%4,%5,%6,%7}, {%8,%9}, {%0,%1,%2,%3};"
                 : "+f"(c[0]), "+f"(c[1]), "+f"(c[2]), "+f"(c[3])
                 : "r"(a0), "r"(a1), "r"(a2), "r"(a3), "r"(b0), "r"(b1));
}

// Shared memory layout (bytes):
//   htt  [4 heads][64 n][136 k] fp16  @ 0        (69632)   n-major (ht^T)
//        (dead after GEMM2 -> reused as K-split stage, 8x1024 floats)
//   attn [128 i][136 k] fp16          @ 69632    (34816)
//   src_s [4][128] f32                @ 104448   (2048)
//   tgt_s [4][128] f32                @ 106496   (2048)
//   maskb [512] u32                   @ 108544   (2048)
// total 110592 B  -> 2 CTAs/SM (221184 <= 228KB)
#define HTS       136
#define HEAD_H    (64 * HTS)           // halves per head
#define ATT_OFF   69632
#define SRC_OFF   104448
#define TGT_OFF   106496
#define MSK_OFF   108544
#define SMEM_BYTES 110592

extern __shared__ char smem_b[];

__global__ __launch_bounds__(THREADS, 2)
void gat_fused_kernel(const float* __restrict__ hg,
                      const float* __restrict__ adjg,
                      const float* __restrict__ Wg,
                      const float* __restrict__ ag,
                      float* __restrict__ outg)
{
    __half* htt_all = (__half*)smem_b;
    __half* attn_h  = (__half*)(smem_b + ATT_OFF);
    float*  src_s   = (float*)(smem_b + SRC_OFF);
    float*  tgt_s   = (float*)(smem_b + TGT_OFF);
    unsigned* maskb = (unsigned*)(smem_b + MSK_OFF);

    const int tid  = threadIdx.x;
    const int lane = tid & 31;
    const int wid  = tid >> 5;
    const int bs   = blockIdx.x;

    const float* hb   = hg   + (size_t)bs * 128 * 64;
    const float* adjb = adjg + (size_t)bs * 128 * 128;
    float*       outb = outg + (size_t)bs * 128 * 64;

    // ---------------- Adjacency -> bitmask (bit set == masked) ----------------
    {
        #pragma unroll
        for (int it = 0; it < 32; it++) {
            int idx = it * 512 + tid;
            unsigned bal = __ballot_sync(0xffffffffu, adjb[idx] < ADJ_THR);
            if (lane == 0) maskb[idx >> 5] = bal;
        }
    }

    // ---------------- GEMM1 (SIMT fp32 exact, W streamed from L2) -------------
    // 16 warps = 4 row-bands x 4 heads. Two sequential 16-row subtiles.
    // Lane tile 4 rows x 8 cols -> acc = 16 ull (32 regs).
    {
        const int rb   = wid >> 2;
        const int head = wid & 3;
        const int rg   = lane >> 3;
        const int cgi  = lane & 7;
        const int cg   = cgi * 8;
        __half* htt_h = htt_all + head * HEAD_H;

        #pragma unroll 1
        for (int s = 0; s < 2; s++) {
            const int row0 = rb * 32 + s * 16 + rg * 4;

            ull acc[4][4];
            #pragma unroll
            for (int r = 0; r < 4; r++)
                #pragma unroll
                for (int p = 0; p < 4; p++) acc[r][p] = pack2(0.f, 0.f);

            #pragma unroll 1
            for (int kq = 0; kq < 16; kq++) {
                float4 a4[4];
                #pragma unroll
                for (int r = 0; r < 4; r++)
                    a4[r] = *(const float4*)&hb[(row0 + r) * 64 + kq * 4];

                #pragma unroll
                for (int kk = 0; kk < 4; kk++) {
                    const int k = kq * 4 + kk;
                    const ulonglong2* wp =
                        (const ulonglong2*)&Wg[k * 256 + head * 64 + cg];
                    ulonglong2 w0 = wp[0];
                    ulonglong2 w1 = wp[1];
                    #pragma unroll
                    for (int r = 0; r < 4; r++) {
                        float av = ((const float*)&a4[r])[kk];
                        ull a2 = pack2(av, av);
                        fma2(acc[r][0], a2, w0.x);
                        fma2(acc[r][1], a2, w0.y);
                        fma2(acc[r][2], a2, w1.x);
                        fma2(acc[r][3], a2, w1.y);
                    }
                }
            }

            // Store htt[head][n][k] fp16, n-major; lane-rotated cols, half2 on k.
            #pragma unroll
            for (int step = 0; step < 8; step++) {
                const int c  = (step + cgi) & 7;
                const int pp = c >> 1;
                float v[4];
                #pragma unroll
                for (int r = 0; r < 4; r++) {
                    float2 f = unpack2(acc[r][pp]);
                    v[r] = (c & 1) ? f.y : f.x;
                }
                __half* dst = htt_h + (cg + c) * HTS + row0;
                *(half2*)dst       = __floats2half2_rn(v[0], v[1]);
                *(half2*)(dst + 2) = __floats2half2_rn(v[2], v[3]);
            }

            // src/tgt epilogue (exact fp32 from register tile)
            float asrc[8], atgt[8];
            #pragma unroll
            for (int j = 0; j < 8; j++) {
                asrc[j] = ag[head * 128 + cg + j];
                atgt[j] = ag[head * 128 + 64 + cg + j];
            }
            #pragma unroll
            for (int r = 0; r < 4; r++) {
                float sv = 0.f, tv = 0.f;
                #pragma unroll
                for (int p = 0; p < 4; p++) {
                    float2 c2 = unpack2(acc[r][p]);
                    sv += c2.x * asrc[2 * p] + c2.y * asrc[2 * p + 1];
                    tv += c2.x * atgt[2 * p] + c2.y * atgt[2 * p + 1];
                }
                #pragma unroll
                for (int m = 4; m >= 1; m >>= 1) {
                    sv += __shfl_xor_sync(0xffffffffu, sv, m);
                    tv += __shfl_xor_sync(0xffffffffu, tv, m);
                }
                if (cgi == 0) {
                    src_s[head * 128 + row0 + r] = sv;
                    tgt_s[head * 128 + row0 + r] = tv;
                }
            }
        }
    }
    __syncthreads();

    // ---------------- Head loop: e-phase -> fp16 MMA GEMM2 --------------------
    // GEMM2: 2-way K-split (kr) x 8 tiles of 32x32 (4 row x 2 col tiles).
    const int kr = wid >> 3;
    const int r0 = ((wid >> 1) & 3) * 32;
    const int c0 = (wid & 1) * 32;
    const int g  = lane >> 2;
    const int t  = lane & 3;

    float C[8][4];
    #pragma unroll
    for (int i = 0; i < 8; i++)
        #pragma unroll
        for (int q = 0; q < 4; q++) C[i][q] = 0.f;

    #pragma unroll 1
    for (int h = 0; h < 4; h++) {
        // ---- e-phase: warp handles rows wid*8..+7; lane covers j=2lane,2lane+1 (+64) ----
        {
            const float* srch = src_s + h * 128;
            const float* tgth = tgt_s + h * 128;
            float2 tA = *(const float2*)&tgth[2 * lane];
            float2 tB = *(const float2*)&tgth[64 + 2 * lane];
            const int mw  = lane >> 4;          // mask word within half
            const int mb  = 2 * (lane & 15);    // bit pos of first of the pair

            #pragma unroll 1
            for (int rr = 0; rr < 8; rr++) {
                const int i = wid * 8 + rr;
                const float si = srch[i];
                unsigned w0 = maskb[i * 4 + mw]       >> mb;
                unsigned w1 = maskb[i * 4 + 2 + mw]   >> mb;
                float p[4];
                {
                    float x = si + tA.x;
                    float sg = rcp_approx(1.0f + __expf(-x));
                    p[0] = (w0 & 1u) ? 0.f : exp01(sg);
                }
                {
                    float x = si + tA.y;
                    float sg = rcp_approx(1.0f + __expf(-x));
                    p[1] = (w0 & 2u) ? 0.f : exp01(sg);
                }
                {
                    float x = si + tB.x;
                    float sg = rcp_approx(1.0f + __expf(-x));
                    p[2] = (w1 & 1u) ? 0.f : exp01(sg);
                }
                {
                    float x = si + tB.y;
                    float sg = rcp_approx(1.0f + __expf(-x));
                    p[3] = (w1 & 2u) ? 0.f : exp01(sg);
                }
                float rs = (p[0] + p[1]) + (p[2] + p[3]);
                #pragma unroll
                for (int m = 16; m >= 1; m >>= 1)
                    rs += __shfl_xor_sync(0xffffffffu, rs, m);
                const float inv = rcp_approx(rs);
                *(half2*)(attn_h + i * HTS + 2 * lane) =
                    __floats2half2_rn(p[0] * inv, p[1] * inv);
                *(half2*)(attn_h + i * HTS + 64 + 2 * lane) =
                    __floats2half2_rn(p[2] * inv, p[3] * inv);
            }
        }
        __syncthreads();

        // ---- GEMM2 slice: C += attn[r0:r0+32, kslice] @ htT[c0:c0+32, kslice] ----
        {
            const __half* htt_h = htt_all + h * HEAD_H;
            #pragma unroll
            for (int ks = 0; ks < 4; ks++) {
                const int k0 = kr * 64 + ks * 16;
                uint32_t A[2][4];
                #pragma unroll
                for (int mt = 0; mt < 2; mt++) {
                    const __half* ar = attn_h + (r0 + mt * 16 + g) * HTS + k0;
                    A[mt][0] = *(const uint32_t*)(ar + 2 * t);
                    A[mt][1] = *(const uint32_t*)(ar + 8 * HTS + 2 * t);
                    A[mt][2] = *(const uint32_t*)(ar + 8 + 2 * t);
                    A[mt][3] = *(const uint32_t*)(ar + 8 * HTS + 8 + 2 * t);
                }
                uint32_t B[4][2];
                #pragma unroll
                for (int nt = 0; nt < 4; nt++) {
                    const __half* br = htt_h + (c0 + nt * 8 + g) * HTS + k0;
                    B[nt][0] = *(const uint32_t*)(br + 2 * t);
                    B[nt][1] = *(const uint32_t*)(br + 8 + 2 * t);
                }
                #pragma unroll
                for (int mt = 0; mt < 2; mt++)
                    #pragma unroll
                    for (int nt = 0; nt < 4; nt++)
                        mma_f16(C[mt * 4 + nt],
                                A[mt][0], A[mt][1], A[mt][2], A[mt][3],
                                B[nt][0], B[nt][1]);
            }
        }
        __syncthreads();   // attn reused by next head
    }

    // ---------------- K-split reduction (stage in dead htt region) ------------
    float* stage = (float*)smem_b;
    if (kr == 1) {
        float* buf = stage + (wid & 7) * 1024;
        #pragma unroll
        for (int i = 0; i < 8; i++)
            #pragma unroll
            for (int q = 0; q < 4; q++)
                buf[(i * 4 + q) * 32 + lane] = C[i][q];
    }
    __syncthreads();

    if (kr == 0) {
        const float* buf = stage + (wid & 7) * 1024;
        #pragma unroll
        for (int mt = 0; mt < 2; mt++) {
            #pragma unroll
            for (int nt = 0; nt < 4; nt++) {
                const int ti = mt * 4 + nt;
                float v0 = C[ti][0] + buf[(ti * 4 + 0) * 32 + lane];
                float v1 = C[ti][1] + buf[(ti * 4 + 1) * 32 + lane];
                float v2 = C[ti][2] + buf[(ti * 4 + 2) * 32 + lane];
                float v3 = C[ti][3] + buf[(ti * 4 + 3) * 32 + lane];
                const int row = r0 + mt * 16 + g;
                const int col = c0 + nt * 8 + 2 * t;
                float2 o0; o0.x = v0 * 0.25f; o0.y = v1 * 0.25f;
                float2 o1; o1.x = v2 * 0.25f; o1.y = v3 * 0.25f;
                *(float2*)&outb[row * 64 + col]       = o0;
                *(float2*)&outb[(row + 8) * 64 + col] = o1;
            }
        }
    }
}

extern "C" void kernel_launch(void* const* d_in, const int* in_sizes, int n_in,
                              void* d_out, int out_size)
{
    const float* h   = (const float*)d_in[0];
    const float* adj = (const float*)d_in[1];
    const float* W   = (const float*)d_in[2];
    const float* a   = (const float*)d_in[3];
    float* out = (float*)d_out;

    static bool attr_set = false;
    if (!attr_set) {
        cudaFuncSetAttribute(gat_fused_kernel,
                             cudaFuncAttributeMaxDynamicSharedMemorySize,
                             SMEM_BYTES);
        attr_set = true;
    }

    gat_fused_kernel<<<BATCH_SEQ, THREADS, SMEM_BYTES>>>(h, adj, W, a, out);
}

// round 6
// speedup vs baseline: 1.0747x; 1.0747x over previous
#include <cuda_runtime.h>
#include <cuda_fp16.h>
#include <cstdint>

// Problem constants
#define BATCH_SEQ 640          // B*S = 32*20
#define THREADS   512
#define ADJ_THR   0.05f

typedef unsigned long long ull;

// ---- packed f32x2 helpers ----
__device__ __forceinline__ void fma2(ull& d, ull a, ull b) {
    asm("fma.rn.f32x2 %0, %1, %2, %0;" : "+l"(d) : "l"(a), "l"(b));
}
__device__ __forceinline__ ull pack2(float x, float y) {
    ull r; asm("mov.b64 %0, {%1, %2};" : "=l"(r) : "f"(x), "f"(y)); return r;
}
__device__ __forceinline__ float2 unpack2(ull v) {
    float2 f; asm("mov.b64 {%0, %1}, %2;" : "=f"(f.x), "=f"(f.y) : "l"(v)); return f;
}
__device__ __forceinline__ float rcp_approx(float x) {
    float r; asm("rcp.approx.f32 %0, %1;" : "=f"(r) : "f"(x)); return r;
}
// e^y for y in [0,1]: degree-7 Taylor (max rel err ~2.8e-5)
__device__ __forceinline__ float exp01(float y) {
    float p = 1.9841270e-4f;
    p = fmaf(p, y, 1.3888889e-3f);
    p = fmaf(p, y, 8.3333333e-3f);
    p = fmaf(p, y, 4.1666668e-2f);
    p = fmaf(p, y, 1.6666667e-1f);
    p = fmaf(p, y, 0.5f);
    p = fmaf(p, y, 1.0f);
    p = fmaf(p, y, 1.0f);
    return p;
}
// fp16 mma m16n8k16, fp32 accum
__device__ __forceinline__ void mma_f16(float c[4],
                                        uint32_t a0, uint32_t a1, uint32_t a2, uint32_t a3,
                                        uint32_t b0, uint32_t b1) {
    asm volatile("mma.sync.aligned.m16n8k16.row.col.f32.f16.f16.f32 "
                 "{%0,%1,%2,%3}, {%4,%5,%6,%7}, {%8,%9}, {%0,%1,%2,%3};"
                 : "+f"(c[0]), "+f"(c[1]), "+f"(c[2]), "+f"(c[3])
                 : "r"(a0), "r"(a1), "r"(a2), "r"(a3), "r"(b0), "r"(b1));
}

// Shared memory layout (bytes):
//   htt  [4 heads][64 n][136 k] fp16  @ 0        (69632)   n-major (ht^T)
//        (dead after GEMM2 -> reused as K-split stage, 8x1024 floats)
//   attn [128 i][136 k] fp16          @ 69632    (34816)
//        (during GEMM1: first 16KB = W slice [64 k][64 col] fp32 for current head)
//   src_s [4][128] f32                @ 104448   (2048)
//   tgt_s [4][128] f32                @ 106496   (2048)
//   maskb [512] u32                   @ 108544   (2048)
// total 110592 B  -> 2 CTAs/SM
#define HTS       136
#define HEAD_H    (64 * HTS)           // halves per head
#define ATT_OFF   69632
#define SRC_OFF   104448
#define TGT_OFF   106496
#define MSK_OFF   108544
#define SMEM_BYTES 110592

extern __shared__ char smem_b[];

__global__ __launch_bounds__(THREADS, 2)
void gat_fused_kernel(const float* __restrict__ hg,
                      const float* __restrict__ adjg,
                      const float* __restrict__ Wg,
                      const float* __restrict__ ag,
                      float* __restrict__ outg)
{
    __half* htt_all = (__half*)smem_b;
    __half* attn_h  = (__half*)(smem_b + ATT_OFF);
    float*  Wbuf    = (float*)(smem_b + ATT_OFF);    // union with attn (GEMM1 phase)
    float*  src_s   = (float*)(smem_b + SRC_OFF);
    float*  tgt_s   = (float*)(smem_b + TGT_OFF);
    unsigned* maskb = (unsigned*)(smem_b + MSK_OFF);

    const int tid  = threadIdx.x;
    const int lane = tid & 31;
    const int wid  = tid >> 5;
    const int bs   = blockIdx.x;

    const float* hb   = hg   + (size_t)bs * 128 * 64;
    const float* adjb = adjg + (size_t)bs * 128 * 128;
    float*       outb = outg + (size_t)bs * 128 * 64;

    // ---------------- Adjacency -> bitmask (bit set == masked) ----------------
    {
        #pragma unroll
        for (int it = 0; it < 32; it++) {
            int idx = it * 512 + tid;
            unsigned bal = __ballot_sync(0xffffffffu, adjb[idx] < ADJ_THR);
            if (lane == 0) maskb[idx >> 5] = bal;
        }
    }

    // ---------------- GEMM1 (SIMT fp32 exact): per-head loop, W slice in smem --
    // All 16 warps on one head at a time. Warp = rows wid*8..+7.
    // Lane: rg = lane>>3 (2 rows), cgi = lane&7 (8 cols). acc[2][4] ull.
    {
        const int rg   = lane >> 3;
        const int cgi  = lane & 7;
        const int cg   = cgi * 8;
        const int row0 = wid * 8 + rg * 2;

        #pragma unroll 1
        for (int head = 0; head < 4; head++) {
            __syncthreads();   // previous head's Wbuf reads complete
            // Stage W[:, head*64 .. +64) into Wbuf (coalesced float4)
            {
                float4* dst = (float4*)Wbuf;
                #pragma unroll
                for (int i = 0; i < 2; i++) {
                    int idx = i * 512 + tid;
                    int k   = idx >> 4;
                    int c4  = idx & 15;
                    dst[idx] = *(const float4*)&Wg[k * 256 + head * 64 + c4 * 4];
                }
            }
            __syncthreads();

            ull acc[2][4];
            #pragma unroll
            for (int r = 0; r < 2; r++)
                #pragma unroll
                for (int p = 0; p < 4; p++) acc[r][p] = pack2(0.f, 0.f);

            #pragma unroll 1
            for (int kq = 0; kq < 16; kq++) {
                float4 a0 = *(const float4*)&hb[row0 * 64 + kq * 4];
                float4 a1 = *(const float4*)&hb[(row0 + 1) * 64 + kq * 4];

                #pragma unroll
                for (int kk = 0; kk < 4; kk++) {
                    const int k = kq * 4 + kk;
                    const ulonglong2* wp = (const ulonglong2*)&Wbuf[k * 64 + cg];
                    ulonglong2 w0 = wp[0];
                    ulonglong2 w1 = wp[1];
                    {
                        float av = ((const float*)&a0)[kk];
                        ull a2 = pack2(av, av);
                        fma2(acc[0][0], a2, w0.x);
                        fma2(acc[0][1], a2, w0.y);
                        fma2(acc[0][2], a2, w1.x);
                        fma2(acc[0][3], a2, w1.y);
                    }
                    {
                        float av = ((const float*)&a1)[kk];
                        ull a2 = pack2(av, av);
                        fma2(acc[1][0], a2, w0.x);
                        fma2(acc[1][1], a2, w0.y);
                        fma2(acc[1][2], a2, w1.x);
                        fma2(acc[1][3], a2, w1.y);
                    }
                }
            }

            // Store htt[head][n][k] fp16 (half2 covers rows row0,row0+1).
            // Lane-rotated cols: bank = 4*perm(cgi) + rg -> conflict-free.
            {
                __half* htt_h = htt_all + head * HEAD_H;
                #pragma unroll
                for (int step = 0; step < 8; step++) {
                    const int c  = (step + cgi) & 7;
                    const int pp = c >> 1;
                    float2 f0 = unpack2(acc[0][pp]);
                    float2 f1 = unpack2(acc[1][pp]);
                    float v0 = (c & 1) ? f0.y : f0.x;
                    float v1 = (c & 1) ? f1.y : f1.x;
                    *(half2*)(htt_h + (cg + c) * HTS + row0) = __floats2half2_rn(v0, v1);
                }
            }

            // src/tgt epilogue (exact fp32 from register tile)
            {
                float asrc[8], atgt[8];
                #pragma unroll
                for (int j = 0; j < 8; j++) {
                    asrc[j] = ag[head * 128 + cg + j];
                    atgt[j] = ag[head * 128 + 64 + cg + j];
                }
                #pragma unroll
                for (int r = 0; r < 2; r++) {
                    float sv = 0.f, tv = 0.f;
                    #pragma unroll
                    for (int p = 0; p < 4; p++) {
                        float2 c2 = unpack2(acc[r][p]);
                        sv += c2.x * asrc[2 * p] + c2.y * asrc[2 * p + 1];
                        tv += c2.x * atgt[2 * p] + c2.y * atgt[2 * p + 1];
                    }
                    #pragma unroll
                    for (int m = 4; m >= 1; m >>= 1) {
                        sv += __shfl_xor_sync(0xffffffffu, sv, m);
                        tv += __shfl_xor_sync(0xffffffffu, tv, m);
                    }
                    if (cgi == 0) {
                        src_s[head * 128 + row0 + r] = sv;
                        tgt_s[head * 128 + row0 + r] = tv;
                    }
                }
            }
        }
    }
    __syncthreads();   // Wbuf reads done; attn region free; htt complete

    // ---------------- Head loop: e-phase -> fp16 MMA GEMM2 --------------------
    // GEMM2: 2-way K-split (kr) x 8 tiles of 32x32 (4 row x 2 col tiles).
    const int kr = wid >> 3;
    const int r0 = ((wid >> 1) & 3) * 32;
    const int c0 = (wid & 1) * 32;
    const int g  = lane >> 2;
    const int t  = lane & 3;

    float C[8][4];
    #pragma unroll
    for (int i = 0; i < 8; i++)
        #pragma unroll
        for (int q = 0; q < 4; q++) C[i][q] = 0.f;

    #pragma unroll 1
    for (int h = 0; h < 4; h++) {
        // ---- e-phase: warp handles rows wid*8..+7; lane covers j=2lane,2lane+1 (+64) ----
        {
            const float* srch = src_s + h * 128;
            const float* tgth = tgt_s + h * 128;
            float2 tA = *(const float2*)&tgth[2 * lane];
            float2 tB = *(const float2*)&tgth[64 + 2 * lane];
            const int mw  = lane >> 4;          // mask word within half
            const int mb  = 2 * (lane & 15);    // bit pos of first of the pair

            #pragma unroll 1
            for (int rr = 0; rr < 8; rr++) {
                const int i = wid * 8 + rr;
                const float si = srch[i];
                unsigned w0 = maskb[i * 4 + mw]       >> mb;
                unsigned w1 = maskb[i * 4 + 2 + mw]   >> mb;
                float p[4];
                {
                    float x = si + tA.x;
                    float sg = rcp_approx(1.0f + __expf(-x));
                    p[0] = (w0 & 1u) ? 0.f : exp01(sg);
                }
                {
                    float x = si + tA.y;
                    float sg = rcp_approx(1.0f + __expf(-x));
                    p[1] = (w0 & 2u) ? 0.f : exp01(sg);
                }
                {
                    float x = si + tB.x;
                    float sg = rcp_approx(1.0f + __expf(-x));
                    p[2] = (w1 & 1u) ? 0.f : exp01(sg);
                }
                {
                    float x = si + tB.y;
                    float sg = rcp_approx(1.0f + __expf(-x));
                    p[3] = (w1 & 2u) ? 0.f : exp01(sg);
                }
                float rs = (p[0] + p[1]) + (p[2] + p[3]);
                #pragma unroll
                for (int m = 16; m >= 1; m >>= 1)
                    rs += __shfl_xor_sync(0xffffffffu, rs, m);
                const float inv = rcp_approx(rs);
                *(half2*)(attn_h + i * HTS + 2 * lane) =
                    __floats2half2_rn(p[0] * inv, p[1] * inv);
                *(half2*)(attn_h + i * HTS + 64 + 2 * lane) =
                    __floats2half2_rn(p[2] * inv, p[3] * inv);
            }
        }
        __syncthreads();

        // ---- GEMM2 slice: C += attn[r0:r0+32, kslice] @ htT[c0:c0+32, kslice] ----
        {
            const __half* htt_h = htt_all + h * HEAD_H;
            #pragma unroll
            for (int ks = 0; ks < 4; ks++) {
                const int k0 = kr * 64 + ks * 16;
                uint32_t A[2][4];
                #pragma unroll
                for (int mt = 0; mt < 2; mt++) {
                    const __half* ar = attn_h + (r0 + mt * 16 + g) * HTS + k0;
                    A[mt][0] = *(const uint32_t*)(ar + 2 * t);
                    A[mt][1] = *(const uint32_t*)(ar + 8 * HTS + 2 * t);
                    A[mt][2] = *(const uint32_t*)(ar + 8 + 2 * t);
                    A[mt][3] = *(const uint32_t*)(ar + 8 * HTS + 8 + 2 * t);
                }
                uint32_t B[4][2];
                #pragma unroll
                for (int nt = 0; nt < 4; nt++) {
                    const __half* br = htt_h + (c0 + nt * 8 + g) * HTS + k0;
                    B[nt][0] = *(const uint32_t*)(br + 2 * t);
                    B[nt][1] = *(const uint32_t*)(br + 8 + 2 * t);
                }
                #pragma unroll
                for (int mt = 0; mt < 2; mt++)
                    #pragma unroll
                    for (int nt = 0; nt < 4; nt++)
                        mma_f16(C[mt * 4 + nt],
                                A[mt][0], A[mt][1], A[mt][2], A[mt][3],
                                B[nt][0], B[nt][1]);
            }
        }
        __syncthreads();   // attn reused by next head
    }

    // ---------------- K-split reduction (stage in dead htt region) ------------
    float* stage = (float*)smem_b;
    if (kr == 1) {
        float* buf = stage + (wid & 7) * 1024;
        #pragma unroll
        for (int i = 0; i < 8; i++)
            #pragma unroll
            for (int q = 0; q < 4; q++)
                buf[(i * 4 + q) * 32 + lane] = C[i][q];
    }
    __syncthreads();

    if (kr == 0) {
        const float* buf = stage + (wid & 7) * 1024;
        #pragma unroll
        for (int mt = 0; mt < 2; mt++) {
            #pragma unroll
            for (int nt = 0; nt < 4; nt++) {
                const int ti = mt * 4 + nt;
                float v0 = C[ti][0] + buf[(ti * 4 + 0) * 32 + lane];
                float v1 = C[ti][1] + buf[(ti * 4 + 1) * 32 + lane];
                float v2 = C[ti][2] + buf[(ti * 4 + 2) * 32 + lane];
                float v3 = C[ti][3] + buf[(ti * 4 + 3) * 32 + lane];
                const int row = r0 + mt * 16 + g;
                const int col = c0 + nt * 8 + 2 * t;
                float2 o0; o0.x = v0 * 0.25f; o0.y = v1 * 0.25f;
                float2 o1; o1.x = v2 * 0.25f; o1.y = v3 * 0.25f;
                *(float2*)&outb[row * 64 + col]       = o0;
                *(float2*)&outb[(row + 8) * 64 + col] = o1;
            }
        }
    }
}

extern "C" void kernel_launch(void* const* d_in, const int* in_sizes, int n_in,
                              void* d_out, int out_size)
{
    const float* h   = (const float*)d_in[0];
    const float* adj = (const float*)d_in[1];
    const float* W   = (const float*)d_in[2];
    const float* a   = (const float*)d_in[3];
    float* out = (float*)d_out;

    static bool attr_set = false;
    if (!attr_set) {
        cudaFuncSetAttribute(gat_fused_kernel,
                             cudaFuncAttributeMaxDynamicSharedMemorySize,
                             SMEM_BYTES);
        attr_set = true;
    }

    gat_fused_kernel<<<BATCH_SEQ, THREADS, SMEM_BYTES>>>(h, adj, W, a, out);
}

// round 7
// speedup vs baseline: 1.4389x; 1.3389x over previous
#include <cuda_runtime.h>
#include <cuda_fp16.h>
#include <cstdint>

// Problem constants
#define BATCH_SEQ 640          // B*S = 32*20
#define THREADS   256
#define ADJ_THR   0.05f

typedef unsigned long long ull;

// ---- packed f32x2 helpers ----
__device__ __forceinline__ void fma2(ull& d, ull a, ull b) {
    asm("fma.rn.f32x2 %0, %1, %2, %0;" : "+l"(d) : "l"(a), "l"(b));
}
__device__ __forceinline__ ull pack2(float x, float y) {
    ull r; asm("mov.b64 %0, {%1, %2};" : "=l"(r) : "f"(x), "f"(y)); return r;
}
__device__ __forceinline__ float2 unpack2(ull v) {
    float2 f; asm("mov.b64 {%0, %1}, %2;" : "=f"(f.x), "=f"(f.y) : "l"(v)); return f;
}
__device__ __forceinline__ float rcp_approx(float x) {
    float r; asm("rcp.approx.f32 %0, %1;" : "=f"(r) : "f"(x)); return r;
}
// fp16 mma m16n8k16, fp32 accum
__device__ __forceinline__ void mma_f16(float c[4],
                                        uint32_t a0, uint32_t a1, uint32_t a2, uint32_t a3,
                                        uint32_t b0, uint32_t b1) {
    asm volatile("mma.sync.aligned.m16n8k16.row.col.f32.f16.f16.f32 "
                 "{%0,%1,%2,%3}, {%4,%5,%6,%7}, {%8,%9}, {%0,%1,%2,%3};"
                 : "+f"(c[0]), "+f"(c[1]), "+f"(c[2]), "+f"(c[3])
                 : "r"(a0), "r"(a1), "r"(a2), "r"(a3), "r"(b0), "r"(b1));
}

// Shared memory layout (bytes):
//   htt  [4 heads][64 n][136 k] fp16  @ 0        (69632)   n-major (ht^T)
//        (dead after GEMM2 -> reused as K-split stage, 4x2048 floats)
//   attn [128 i][136 k] fp16          @ 69632    (34816)
//        (during GEMM1: first 32KB = W slice [64 k][128 col] fp32 for head pair)
//   src_s [4][128] f32                @ 104448   (2048)
//   tgt_s [4][128] f32                @ 106496   (2048)
//   maskb [512] u32                   @ 108544   (2048)
// total 110592 B  -> 2 CTAs/SM (221184 incl. static margin OK)
#define HTS       136
#define HEAD_H    (64 * HTS)           // halves per head
#define ATT_OFF   69632
#define SRC_OFF   104448
#define TGT_OFF   106496
#define MSK_OFF   108544
#define SMEM_BYTES 110592

extern __shared__ char smem_b[];

__global__ __launch_bounds__(THREADS, 2)
void gat_fused_kernel(const float* __restrict__ hg,
                      const float* __restrict__ adjg,
                      const float* __restrict__ Wg,
                      const float* __restrict__ ag,
                      float* __restrict__ outg)
{
    __half* htt_all = (__half*)smem_b;
    __half* attn_h  = (__half*)(smem_b + ATT_OFF);
    float*  Wbuf    = (float*)(smem_b + ATT_OFF);    // union with attn (GEMM1 phase)
    float*  src_s   = (float*)(smem_b + SRC_OFF);
    float*  tgt_s   = (float*)(smem_b + TGT_OFF);
    unsigned* maskb = (unsigned*)(smem_b + MSK_OFF);

    const int tid  = threadIdx.x;
    const int lane = tid & 31;
    const int wid  = tid >> 5;      // 0..7
    const int bs   = blockIdx.x;

    const float* hb   = hg   + (size_t)bs * 128 * 64;
    const float* adjb = adjg + (size_t)bs * 128 * 128;
    float*       outb = outg + (size_t)bs * 128 * 64;

    // ---------------- Adjacency -> bitmask (bit set == masked) ----------------
    {
        #pragma unroll
        for (int it = 0; it < 64; it++) {
            int idx = it * 256 + tid;
            unsigned bal = __ballot_sync(0xffffffffu, adjb[idx] < ADJ_THR);
            if (lane == 0) maskb[idx >> 5] = bal;
        }
    }

    // ---------------- GEMM1 (SIMT fp32 exact): head-pair loop -----------------
    // 8 warps x 16 rows = 128 rows. Lane owns cols {2L,2L+1} of both heads in
    // the pair. acc[16][2] (row x head) = 64 regs. W slice (64k x 128c) in smem.
    {
        const int row0 = wid * 16;

        #pragma unroll 1
        for (int hp = 0; hp < 2; hp++) {
            __syncthreads();   // previous phase's Wbuf/attn reads complete
            // Stage W[:, hp*128 .. +128) into Wbuf (coalesced float4)
            {
                float4* dst = (float4*)Wbuf;
                #pragma unroll
                for (int j = 0; j < 8; j++) {
                    int idx = j * 256 + tid;
                    int k   = idx >> 5;
                    int c4  = idx & 31;
                    dst[idx] = *(const float4*)&Wg[k * 256 + hp * 128 + c4 * 4];
                }
            }
            __syncthreads();

            ull acc[16][2];
            #pragma unroll
            for (int r = 0; r < 16; r++) {
                acc[r][0] = pack2(0.f, 0.f);
                acc[r][1] = pack2(0.f, 0.f);
            }

            #pragma unroll 1
            for (int kq = 0; kq < 16; kq++) {
                // Hoist this kq's W values (4 kk x 2 heads)
                ull wreg[4][2];
                #pragma unroll
                for (int kk = 0; kk < 4; kk++) {
                    const float* wr = &Wbuf[(kq * 4 + kk) * 128 + 2 * lane];
                    wreg[kk][0] = *(const ull*)wr;
                    wreg[kk][1] = *(const ull*)(wr + 64);
                }
                #pragma unroll
                for (int r = 0; r < 16; r++) {
                    float4 a4 = *(const float4*)&hb[(row0 + r) * 64 + kq * 4];
                    #pragma unroll
                    for (int kk = 0; kk < 4; kk++) {
                        float av = ((const float*)&a4)[kk];
                        ull a2 = pack2(av, av);
                        fma2(acc[r][0], a2, wreg[kk][0]);
                        fma2(acc[r][1], a2, wreg[kk][1]);
                    }
                }
            }

            // Store htt + src/tgt epilogue for both heads of the pair
            #pragma unroll
            for (int hh = 0; hh < 2; hh++) {
                const int head = hp * 2 + hh;
                __half* htt_h = htt_all + head * HEAD_H;
                // Stores: n = 2L, 2L+1; 8 row-chunks (half2), lane-rotated.
                #pragma unroll
                for (int c = 0; c < 8; c++) {
                    const int ch = (c + (lane >> 2)) & 7;
                    float2 f0 = unpack2(acc[2 * ch][hh]);
                    float2 f1 = unpack2(acc[2 * ch + 1][hh]);
                    *(half2*)(htt_h + (2 * lane) * HTS + row0 + 2 * ch) =
                        __floats2half2_rn(f0.x, f1.x);
                    *(half2*)(htt_h + (2 * lane + 1) * HTS + row0 + 2 * ch) =
                        __floats2half2_rn(f0.y, f1.y);
                }
                // src/tgt: exact fp32 dot with a-vectors, full-warp reduce
                float2 as = *(const float2*)&ag[head * 128 + 2 * lane];
                float2 at = *(const float2*)&ag[head * 128 + 64 + 2 * lane];
                #pragma unroll
                for (int r = 0; r < 16; r++) {
                    float2 c2 = unpack2(acc[r][hh]);
                    float sv = c2.x * as.x + c2.y * as.y;
                    float tv = c2.x * at.x + c2.y * at.y;
                    #pragma unroll
                    for (int m = 16; m >= 1; m >>= 1) {
                        sv += __shfl_xor_sync(0xffffffffu, sv, m);
                        tv += __shfl_xor_sync(0xffffffffu, tv, m);
                    }
                    if (lane == 0) {
                        src_s[head * 128 + row0 + r] = sv;
                        tgt_s[head * 128 + row0 + r] = tv;
                    }
                }
            }
        }
    }
    __syncthreads();   // Wbuf reads done; attn region free; htt complete

    // ---------------- Head loop: e-phase -> fp16 MMA GEMM2 --------------------
    // GEMM2: 2-way K-split (kr = wid>>2) x 4 row-quads (quad = wid&3, 32 rows),
    // each warp covers all 64 cols. C[16][4] = 64 regs, accumulated over heads.
    const int kr   = wid >> 2;
    const int quad = wid & 3;
    const int r0   = quad * 32;
    const int g    = lane >> 2;
    const int t    = lane & 3;

    float C[16][4];
    #pragma unroll
    for (int i = 0; i < 16; i++)
        #pragma unroll
        for (int q = 0; q < 4; q++) C[i][q] = 0.f;

    #pragma unroll 1
    for (int h = 0; h < 4; h++) {
        // ---- e-phase: warp handles rows wid*16..+15; lane covers j=2L,2L+1 (+64) ----
        {
            const float* srch = src_s + h * 128;
            const float* tgth = tgt_s + h * 128;
            float2 tA = *(const float2*)&tgth[2 * lane];
            float2 tB = *(const float2*)&tgth[64 + 2 * lane];
            const int mw  = lane >> 4;
            const int mb  = 2 * (lane & 15);

            #pragma unroll 1
            for (int rr = 0; rr < 16; rr++) {
                const int i = wid * 16 + rr;
                const float si = srch[i];
                unsigned w0 = maskb[i * 4 + mw]     >> mb;
                unsigned w1 = maskb[i * 4 + 2 + mw] >> mb;
                float p[4];
                {
                    float sg = rcp_approx(1.0f + __expf(-(si + tA.x)));
                    p[0] = (w0 & 1u) ? 0.f : __expf(sg);
                }
                {
                    float sg = rcp_approx(1.0f + __expf(-(si + tA.y)));
                    p[1] = (w0 & 2u) ? 0.f : __expf(sg);
                }
                {
                    float sg = rcp_approx(1.0f + __expf(-(si + tB.x)));
                    p[2] = (w1 & 1u) ? 0.f : __expf(sg);
                }
                {
                    float sg = rcp_approx(1.0f + __expf(-(si + tB.y)));
                    p[3] = (w1 & 2u) ? 0.f : __expf(sg);
                }
                float rs = (p[0] + p[1]) + (p[2] + p[3]);
                #pragma unroll
                for (int m = 16; m >= 1; m >>= 1)
                    rs += __shfl_xor_sync(0xffffffffu, rs, m);
                const float inv = rcp_approx(rs);
                *(half2*)(attn_h + i * HTS + 2 * lane) =
                    __floats2half2_rn(p[0] * inv, p[1] * inv);
                *(half2*)(attn_h + i * HTS + 64 + 2 * lane) =
                    __floats2half2_rn(p[2] * inv, p[3] * inv);
            }
        }
        __syncthreads();

        // ---- GEMM2 slice: C += attn[r0:r0+32, kslice] @ htT[0:64, kslice] ----
        {
            const __half* htt_h = htt_all + h * HEAD_H;
            #pragma unroll
            for (int ks = 0; ks < 4; ks++) {
                const int k0 = kr * 64 + ks * 16;
                uint32_t A[2][4];
                #pragma unroll
                for (int mt = 0; mt < 2; mt++) {
                    const __half* ar = attn_h + (r0 + mt * 16 + g) * HTS + k0;
                    A[mt][0] = *(const uint32_t*)(ar + 2 * t);
                    A[mt][1] = *(const uint32_t*)(ar + 8 * HTS + 2 * t);
                    A[mt][2] = *(const uint32_t*)(ar + 8 + 2 * t);
                    A[mt][3] = *(const uint32_t*)(ar + 8 * HTS + 8 + 2 * t);
                }
                #pragma unroll
                for (int nh = 0; nh < 2; nh++) {
                    uint32_t B[4][2];
                    #pragma unroll
                    for (int nt = 0; nt < 4; nt++) {
                        const __half* br =
                            htt_h + (nh * 32 + nt * 8 + g) * HTS + k0;
                        B[nt][0] = *(const uint32_t*)(br + 2 * t);
                        B[nt][1] = *(const uint32_t*)(br + 8 + 2 * t);
                    }
                    #pragma unroll
                    for (int mt = 0; mt < 2; mt++)
                        #pragma unroll
                        for (int nt = 0; nt < 4; nt++)
                            mma_f16(C[mt * 8 + nh * 4 + nt],
                                    A[mt][0], A[mt][1], A[mt][2], A[mt][3],
                                    B[nt][0], B[nt][1]);
                }
            }
        }
        __syncthreads();   // attn reused by next head
    }

    // ---------------- K-split reduction (stage in dead htt region) ------------
    float* stage = (float*)smem_b;
    if (kr == 1) {
        float* buf = stage + quad * 2048;
        #pragma unroll
        for (int i = 0; i < 16; i++)
            #pragma unroll
            for (int q = 0; q < 4; q++)
                buf[(i * 4 + q) * 32 + lane] = C[i][q];
    }
    __syncthreads();

    if (kr == 0) {
        const float* buf = stage + quad * 2048;
        #pragma unroll
        for (int mt = 0; mt < 2; mt++) {
            #pragma unroll
            for (int nt8 = 0; nt8 < 8; nt8++) {
                const int ti = mt * 8 + nt8;
                float v0 = C[ti][0] + buf[(ti * 4 + 0) * 32 + lane];
                float v1 = C[ti][1] + buf[(ti * 4 + 1) * 32 + lane];
                float v2 = C[ti][2] + buf[(ti * 4 + 2) * 32 + lane];
                float v3 = C[ti][3] + buf[(ti * 4 + 3) * 32 + lane];
                const int row = r0 + mt * 16 + g;
                const int col = nt8 * 8 + 2 * t;
                float2 o0; o0.x = v0 * 0.25f; o0.y = v1 * 0.25f;
                float2 o1; o1.x = v2 * 0.25f; o1.y = v3 * 0.25f;
                *(float2*)&outb[row * 64 + col]       = o0;
                *(float2*)&outb[(row + 8) * 64 + col] = o1;
            }
        }
    }
}

extern "C" void kernel_launch(void* const* d_in, const int* in_sizes, int n_in,
                              void* d_out, int out_size)
{
    const float* h   = (const float*)d_in[0];
    const float* adj = (const float*)d_in[1];
    const float* W   = (const float*)d_in[2];
    const float* a   = (const float*)d_in[3];
    float* out = (float*)d_out;

    static bool attr_set = false;
    if (!attr_set) {
        cudaFuncSetAttribute(gat_fused_kernel,
                             cudaFuncAttributeMaxDynamicSharedMemorySize,
                             SMEM_BYTES);
        attr_set = true;
    }

    gat_fused_kernel<<<BATCH_SEQ, THREADS, SMEM_BYTES>>>(h, adj, W, a, out);
}

// round 8
// speedup vs baseline: 2.5638x; 1.7818x over previous
#include <cuda_runtime.h>
#include <cuda_fp16.h>
#include <cstdint>

// Problem constants
#define BATCH_SEQ 640          // B*S = 32*20
#define THREADS   256
#define ADJ_THR   0.05f

__device__ __forceinline__ float rcp_approx(float x) {
    float r; asm("rcp.approx.f32 %0, %1;" : "=f"(r) : "f"(x)); return r;
}
// fp16 mma m16n8k16, fp32 accum
__device__ __forceinline__ void mma_f16(float c[4],
                                        uint32_t a0, uint32_t a1, uint32_t a2, uint32_t a3,
                                        uint32_t b0, uint32_t b1) {
    asm volatile("mma.sync.aligned.m16n8k16.row.col.f32.f16.f16.f32 "
                 "{%0,%1,%2,%3}, {%4,%5,%6,%7}, {%8,%9}, {%0,%1,%2,%3};"
                 : "+f"(c[0]), "+f"(c[1]), "+f"(c[2]), "+f"(c[3])
                 : "r"(a0), "r"(a1), "r"(a2), "r"(a3), "r"(b0), "r"(b1));
}

// Shared memory layout (bytes):
//   htt  [256 o][136 k-halves] fp16  @ 0        (69632)  o-major (ht^T), o = head*64+d
//        (dead after GEMM2 -> reused as K-split stage, 4x2048 floats)
//   ATT region @ 69632 (34816):
//     GEMM1 phase: hs [128 row][64 k] fp16 XOR-swz @69632 (16384)
//                  Wt [64 o'][64 k] fp16 XOR-swz   @86016 (8192)
//     attn phase : attn [128 i][136 k] fp16        @69632 (34816)
//   src_s [4][128] f32  @ 104448 (2048)
//   tgt_s [4][128] f32  @ 106496 (2048)
//   maskb [512] u32     @ 108544 (2048)
//   a_s   [512] f32     @ 110592 (2048)
// total 112640 B -> 2 CTAs/SM (225280 <= 228KB)
#define HTS       136
#define ATT_OFF   69632
#define HS_OFF    69632
#define WT_OFF    86016
#define SRC_OFF   104448
#define TGT_OFF   106496
#define MSK_OFF   108544
#define AS_OFF    110592
#define SMEM_BYTES 112640

extern __shared__ char smem_b[];

__global__ __launch_bounds__(THREADS, 2)
void gat_fused_kernel(const float* __restrict__ hg,
                      const float* __restrict__ adjg,
                      const float* __restrict__ Wg,
                      const float* __restrict__ ag,
                      float* __restrict__ outg)
{
    __half* htt    = (__half*)smem_b;
    __half* attn_h = (__half*)(smem_b + ATT_OFF);
    __half* hs     = (__half*)(smem_b + HS_OFF);
    __half* Wt     = (__half*)(smem_b + WT_OFF);
    float*  src_s  = (float*)(smem_b + SRC_OFF);
    float*  tgt_s  = (float*)(smem_b + TGT_OFF);
    unsigned* maskb = (unsigned*)(smem_b + MSK_OFF);
    float*  a_s    = (float*)(smem_b + AS_OFF);

    const int tid  = threadIdx.x;
    const int lane = tid & 31;
    const int wid  = tid >> 5;      // 0..7
    const int g    = lane >> 2;     // 0..7
    const int t    = lane & 3;      // 0..3
    const int bs   = blockIdx.x;

    const float* hb   = hg   + (size_t)bs * 128 * 64;
    const float* adjb = adjg + (size_t)bs * 128 * 128;
    float*       outb = outg + (size_t)bs * 128 * 64;

    // ---------------- Prologue: a_s, adjacency bitmask, hs (fp16 h) -----------
    a_s[tid]       = ag[tid];
    a_s[256 + tid] = ag[256 + tid];

    #pragma unroll 8
    for (int it = 0; it < 64; it++) {
        int idx = it * 256 + tid;
        unsigned bal = __ballot_sync(0xffffffffu, adjb[idx] < ADJ_THR);
        if (lane == 0) maskb[idx >> 5] = bal;
    }

    // hs[row][k ^ 8*(row&7)] fp16
    #pragma unroll
    for (int it = 0; it < 8; it++) {
        int idx = it * 256 + tid;
        int row = idx >> 4;
        int k4  = (idx & 15) * 4;
        float4 v = *(const float4*)&hb[row * 64 + k4];
        __half* p = hs + row * 64 + (k4 ^ (8 * (row & 7)));
        *(half2*)p       = __floats2half2_rn(v.x, v.y);
        *(half2*)(p + 2) = __floats2half2_rn(v.z, v.w);
    }

    // ---------------- GEMM1 on tensor pipe: htt[o][row] = W^T @ h^T -----------
    // 4 passes (one per head / 64-o slice). Warp tile: 32 o x 32 rows.
    {
        const int ow = (wid & 1) * 32;     // o offset within slice
        const int rb = wid >> 1;           // row block (32 rows)

        #pragma unroll 1
        for (int p = 0; p < 4; p++) {
            if (p > 0) __syncthreads();    // pass p-1 frag reads done
            // Stage Wt[o'][k ^ 8*(o'&7)] = W[k][p*64+o'] fp16
            #pragma unroll
            for (int it = 0; it < 4; it++) {
                int idx = it * 256 + tid;
                int k   = idx >> 4;
                int o4  = (idx & 15) * 4;
                float4 v = *(const float4*)&Wg[k * 256 + p * 64 + o4];
                Wt[(o4 + 0) * 64 + (k ^ (8 * ((o4 + 0) & 7)))] = __float2half_rn(v.x);
                Wt[(o4 + 1) * 64 + (k ^ (8 * ((o4 + 1) & 7)))] = __float2half_rn(v.y);
                Wt[(o4 + 2) * 64 + (k ^ (8 * ((o4 + 2) & 7)))] = __float2half_rn(v.z);
                Wt[(o4 + 3) * 64 + (k ^ (8 * ((o4 + 3) & 7)))] = __float2half_rn(v.w);
            }
            __syncthreads();               // hs (first pass) + Wt visible

            float C[8][4];
            #pragma unroll
            for (int i = 0; i < 8; i++)
                #pragma unroll
                for (int q = 0; q < 4; q++) C[i][q] = 0.f;

            #pragma unroll
            for (int ks = 0; ks < 4; ks++) {
                const int k0 = ks * 16;
                uint32_t A[2][4];
                #pragma unroll
                for (int mt = 0; mt < 2; mt++) {
                    const int o  = ow + mt * 16 + g;
                    const int sw = 8 * (o & 7);          // (o+8)&7 == o&7
                    const __half* ba = Wt + o * 64;
                    A[mt][0] = *(const uint32_t*)(ba + ((k0 + 2 * t) ^ sw));
                    A[mt][1] = *(const uint32_t*)(ba + 8 * 64 + ((k0 + 2 * t) ^ sw));
                    A[mt][2] = *(const uint32_t*)(ba + ((k0 + 8 + 2 * t) ^ sw));
                    A[mt][3] = *(const uint32_t*)(ba + 8 * 64 + ((k0 + 8 + 2 * t) ^ sw));
                }
                #pragma unroll
                for (int nt = 0; nt < 4; nt++) {
                    const int n = rb * 32 + nt * 8 + g;  // n&7 == g
                    const __half* bb = hs + n * 64;
                    uint32_t b0 = *(const uint32_t*)(bb + ((k0 + 2 * t) ^ (8 * g)));
                    uint32_t b1 = *(const uint32_t*)(bb + ((k0 + 8 + 2 * t) ^ (8 * g)));
                    mma_f16(C[nt],     A[0][0], A[0][1], A[0][2], A[0][3], b0, b1);
                    mma_f16(C[4 + nt], A[1][0], A[1][1], A[1][2], A[1][3], b0, b1);
                }
            }

            // Store htt (half2, conflict-free: bank = 4g+t+const per instr)
            #pragma unroll
            for (int mt = 0; mt < 2; mt++) {
                #pragma unroll
                for (int nt = 0; nt < 4; nt++) {
                    const float* c = C[mt * 4 + nt];
                    const int o   = p * 64 + ow + mt * 16 + g;
                    const int row = rb * 32 + nt * 8 + 2 * t;
                    *(half2*)&htt[o * HTS + row] =
                        __floats2half2_rn(c[0], c[1]);
                    *(half2*)&htt[(o + 8) * HTS + row] =
                        __floats2half2_rn(c[2], c[3]);
                }
            }
        }
    }
    __syncthreads();   // htt complete

    // ---------------- src/tgt: exact fp32 dot over htt columns ----------------
    // 8 warps = 4 heads x 2 row-halves. Lane owns rows {2L, 2L+1} of its half.
    {
        const int head = wid >> 1;
        const int rb2  = wid & 1;
        const int rowoff = rb2 * 64 + 2 * lane;
        float s0 = 0.f, s1 = 0.f, t0 = 0.f, t1 = 0.f;
        #pragma unroll 8
        for (int o = 0; o < 64; o++) {
            half2 v = *(const half2*)&htt[(head * 64 + o) * HTS + rowoff];
            float2 f = __half22float2(v);
            float av = a_s[head * 128 + o];
            float bv = a_s[head * 128 + 64 + o];
            s0 = fmaf(f.x, av, s0); s1 = fmaf(f.y, av, s1);
            t0 = fmaf(f.x, bv, t0); t1 = fmaf(f.y, bv, t1);
        }
        float2 sv; sv.x = s0; sv.y = s1;
        float2 tv; tv.x = t0; tv.y = t1;
        *(float2*)&src_s[head * 128 + rowoff] = sv;
        *(float2*)&tgt_s[head * 128 + rowoff] = tv;
    }
    __syncthreads();   // src/tgt ready; hs/Wt dead -> attn region free

    // ---------------- Head loop: e-phase -> fp16 MMA GEMM2 --------------------
    // GEMM2: 2-way K-split (kr = wid>>2) x 4 row-quads; C accumulated over heads.
    const int kr   = wid >> 2;
    const int quad = wid & 3;
    const int r0   = quad * 32;

    float C[16][4];
    #pragma unroll
    for (int i = 0; i < 16; i++)
        #pragma unroll
        for (int q = 0; q < 4; q++) C[i][q] = 0.f;

    #pragma unroll 1
    for (int h = 0; h < 4; h++) {
        // ---- e-phase: warp handles rows wid*16..+15; lane covers j=2L,2L+1 (+64) ----
        {
            const float* srch = src_s + h * 128;
            const float* tgth = tgt_s + h * 128;
            float2 tA = *(const float2*)&tgth[2 * lane];
            float2 tB = *(const float2*)&tgth[64 + 2 * lane];
            const int mw = lane >> 4;
            const int mb = 2 * (lane & 15);

            #pragma unroll 1
            for (int rr = 0; rr < 16; rr++) {
                const int i = wid * 16 + rr;
                const float si = srch[i];
                unsigned w0 = maskb[i * 4 + mw]     >> mb;
                unsigned w1 = maskb[i * 4 + 2 + mw] >> mb;
                float p[4];
                {
                    float sg = rcp_approx(1.0f + __expf(-(si + tA.x)));
                    p[0] = (w0 & 1u) ? 0.f : __expf(sg);
                }
                {
                    float sg = rcp_approx(1.0f + __expf(-(si + tA.y)));
                    p[1] = (w0 & 2u) ? 0.f : __expf(sg);
                }
                {
                    float sg = rcp_approx(1.0f + __expf(-(si + tB.x)));
                    p[2] = (w1 & 1u) ? 0.f : __expf(sg);
                }
                {
                    float sg = rcp_approx(1.0f + __expf(-(si + tB.y)));
                    p[3] = (w1 & 2u) ? 0.f : __expf(sg);
                }
                float rs = (p[0] + p[1]) + (p[2] + p[3]);
                #pragma unroll
                for (int m = 16; m >= 1; m >>= 1)
                    rs += __shfl_xor_sync(0xffffffffu, rs, m);
                const float inv = rcp_approx(rs);
                *(half2*)(attn_h + i * HTS + 2 * lane) =
                    __floats2half2_rn(p[0] * inv, p[1] * inv);
                *(half2*)(attn_h + i * HTS + 64 + 2 * lane) =
                    __floats2half2_rn(p[2] * inv, p[3] * inv);
            }
        }
        __syncthreads();

        // ---- GEMM2 slice: C += attn[r0:r0+32, kslice] @ htt[h*64.., kslice] ----
        {
            const __half* htt_h = htt + (h * 64) * HTS;
            #pragma unroll
            for (int ks = 0; ks < 4; ks++) {
                const int k0 = kr * 64 + ks * 16;
                uint32_t A[2][4];
                #pragma unroll
                for (int mt = 0; mt < 2; mt++) {
                    const __half* ar = attn_h + (r0 + mt * 16 + g) * HTS + k0;
                    A[mt][0] = *(const uint32_t*)(ar + 2 * t);
                    A[mt][1] = *(const uint32_t*)(ar + 8 * HTS + 2 * t);
                    A[mt][2] = *(const uint32_t*)(ar + 8 + 2 * t);
                    A[mt][3] = *(const uint32_t*)(ar + 8 * HTS + 8 + 2 * t);
                }
                #pragma unroll
                for (int nh = 0; nh < 2; nh++) {
                    uint32_t B[4][2];
                    #pragma unroll
                    for (int nt = 0; nt < 4; nt++) {
                        const __half* br = htt_h + (nh * 32 + nt * 8 + g) * HTS + k0;
                        B[nt][0] = *(const uint32_t*)(br + 2 * t);
                        B[nt][1] = *(const uint32_t*)(br + 8 + 2 * t);
                    }
                    #pragma unroll
                    for (int mt = 0; mt < 2; mt++)
                        #pragma unroll
                        for (int nt = 0; nt < 4; nt++)
                            mma_f16(C[mt * 8 + nh * 4 + nt],
                                    A[mt][0], A[mt][1], A[mt][2], A[mt][3],
                                    B[nt][0], B[nt][1]);
                }
            }
        }
        __syncthreads();   // attn reused by next head
    }

    // ---------------- K-split reduction (stage in dead htt region) ------------
    float* stage = (float*)smem_b;
    if (kr == 1) {
        float* buf = stage + quad * 2048;
        #pragma unroll
        for (int i = 0; i < 16; i++)
            #pragma unroll
            for (int q = 0; q < 4; q++)
                buf[(i * 4 + q) * 32 + lane] = C[i][q];
    }
    __syncthreads();

    if (kr == 0) {
        const float* buf = stage + quad * 2048;
        #pragma unroll
        for (int mt = 0; mt < 2; mt++) {
            #pragma unroll
            for (int nt8 = 0; nt8 < 8; nt8++) {
                const int ti = mt * 8 + nt8;
                float v0 = C[ti][0] + buf[(ti * 4 + 0) * 32 + lane];
                float v1 = C[ti][1] + buf[(ti * 4 + 1) * 32 + lane];
                float v2 = C[ti][2] + buf[(ti * 4 + 2) * 32 + lane];
                float v3 = C[ti][3] + buf[(ti * 4 + 3) * 32 + lane];
                const int row = r0 + mt * 16 + g;
                const int col = nt8 * 8 + 2 * t;
                float2 o0; o0.x = v0 * 0.25f; o0.y = v1 * 0.25f;
                float2 o1; o1.x = v2 * 0.25f; o1.y = v3 * 0.25f;
                *(float2*)&outb[row * 64 + col]       = o0;
                *(float2*)&outb[(row + 8) * 64 + col] = o1;
            }
        }
    }
}

extern "C" void kernel_launch(void* const* d_in, const int* in_sizes, int n_in,
                              void* d_out, int out_size)
{
    const float* h   = (const float*)d_in[0];
    const float* adj = (const float*)d_in[1];
    const float* W   = (const float*)d_in[2];
    const float* a   = (const float*)d_in[3];
    float* out = (float*)d_out;

    static bool attr_set = false;
    if (!attr_set) {
        cudaFuncSetAttribute(gat_fused_kernel,
                             cudaFuncAttributeMaxDynamicSharedMemorySize,
                             SMEM_BYTES);
        attr_set = true;
    }

    gat_fused_kernel<<<BATCH_SEQ, THREADS, SMEM_BYTES>>>(h, adj, W, a, out);
}

// round 9
// speedup vs baseline: 2.6729x; 1.0426x over previous
#include <cuda_runtime.h>
#include <cuda_fp16.h>
#include <cstdint>

// Problem constants
#define BATCH_SEQ 640          // B*S = 32*20
#define THREADS   256
#define ADJ_THR   0.05f

__device__ __forceinline__ float rcp_approx(float x) {
    float r; asm("rcp.approx.f32 %0, %1;" : "=f"(r) : "f"(x)); return r;
}
// e^y for y in [0,1]: degree-7 Taylor (max rel err ~2.8e-5)
__device__ __forceinline__ float exp01(float y) {
    float p = 1.9841270e-4f;
    p = fmaf(p, y, 1.3888889e-3f);
    p = fmaf(p, y, 8.3333333e-3f);
    p = fmaf(p, y, 4.1666668e-2f);
    p = fmaf(p, y, 1.6666667e-1f);
    p = fmaf(p, y, 0.5f);
    p = fmaf(p, y, 1.0f);
    p = fmaf(p, y, 1.0f);
    return p;
}
// fp16 mma m16n8k16, fp32 accum
__device__ __forceinline__ void mma_f16(float c[4],
                                        uint32_t a0, uint32_t a1, uint32_t a2, uint32_t a3,
                                        uint32_t b0, uint32_t b1) {
    asm volatile("mma.sync.aligned.m16n8k16.row.col.f32.f16.f16.f32 "
                 "{%0,%1,%2,%3}, {%4,%5,%6,%7}, {%8,%9}, {%0,%1,%2,%3};"
                 : "+f"(c[0]), "+f"(c[1]), "+f"(c[2]), "+f"(c[3])
                 : "r"(a0), "r"(a1), "r"(a2), "r"(a3), "r"(b0), "r"(b1));
}
__device__ __forceinline__ uint32_t cvta_s(const void* p) {
    uint32_t a; asm("{ .reg .u64 t; cvta.to.shared.u64 t, %1; cvt.u32.u64 %0, t; }"
                    : "=r"(a) : "l"(p));
    return a;
}
__device__ __forceinline__ void ldm_x4(uint32_t& r0, uint32_t& r1,
                                       uint32_t& r2, uint32_t& r3, uint32_t a) {
    asm volatile("ldmatrix.sync.aligned.m8n8.x4.shared.b16 {%0,%1,%2,%3}, [%4];"
                 : "=r"(r0), "=r"(r1), "=r"(r2), "=r"(r3) : "r"(a));
}

// Shared memory layout (bytes):
//   htt  [256 o][136 k-halves] fp16  @ 0        (69632)  o-major (ht^T), o = head*64+d
//        (dead after GEMM2 -> reused as K-split stage, 4x2048 floats)
//   ATT region @ 69632 (34816):
//     GEMM1 phase: hs [128 row][64 k] fp16 XOR-swz @69632 (16384)
//                  Wt [64 o'][64 k] fp16 XOR-swz   @86016 (8192)
//     attn phase : attn [128 i][136 k] fp16        @69632 (34816)
//   src_s [4][128] f32  @ 104448 (2048)
//   tgt_s [4][128] f32  @ 106496 (2048)
//   maskb [512] u32     @ 108544 (2048)
//   a_s   [512] f32     @ 110592 (2048)
// total 112640 B -> 2 CTAs/SM
#define HTS       136
#define ATT_OFF   69632
#define HS_OFF    69632
#define WT_OFF    86016
#define SRC_OFF   104448
#define TGT_OFF   106496
#define MSK_OFF   108544
#define AS_OFF    110592
#define SMEM_BYTES 112640

extern __shared__ char smem_b[];

__global__ __launch_bounds__(THREADS, 2)
void gat_fused_kernel(const float* __restrict__ hg,
                      const float* __restrict__ adjg,
                      const float* __restrict__ Wg,
                      const float* __restrict__ ag,
                      float* __restrict__ outg)
{
    __half* htt    = (__half*)smem_b;
    __half* attn_h = (__half*)(smem_b + ATT_OFF);
    __half* hs     = (__half*)(smem_b + HS_OFF);
    __half* Wt     = (__half*)(smem_b + WT_OFF);
    float*  src_s  = (float*)(smem_b + SRC_OFF);
    float*  tgt_s  = (float*)(smem_b + TGT_OFF);
    unsigned* maskb = (unsigned*)(smem_b + MSK_OFF);
    float*  a_s    = (float*)(smem_b + AS_OFF);

    const int tid  = threadIdx.x;
    const int lane = tid & 31;
    const int wid  = tid >> 5;      // 0..7
    const int g    = lane >> 2;     // 0..7
    const int t    = lane & 3;      // 0..3
    const int lrow = lane & 15;     // ldmatrix row within 16
    const int lhi  = lane >> 4;     // ldmatrix k-chunk select
    const int bs   = blockIdx.x;

    const float* hb   = hg   + (size_t)bs * 128 * 64;
    const float* adjb = adjg + (size_t)bs * 128 * 128;
    float*       outb = outg + (size_t)bs * 128 * 64;

    const uint32_t htt_s = cvta_s(htt);
    const uint32_t att_s = cvta_s(attn_h);
    const uint32_t hs_s  = cvta_s(hs);
    const uint32_t wt_s  = cvta_s(Wt);

    // ---------------- Prologue: a_s, adjacency bitmask, hs (fp16 h) -----------
    a_s[tid]       = ag[tid];
    a_s[256 + tid] = ag[256 + tid];

    #pragma unroll 8
    for (int it = 0; it < 64; it++) {
        int idx = it * 256 + tid;
        unsigned bal = __ballot_sync(0xffffffffu, adjb[idx] < ADJ_THR);
        if (lane == 0) maskb[idx >> 5] = bal;
    }

    // hs[row][k ^ 8*(row&7)] fp16
    #pragma unroll
    for (int it = 0; it < 8; it++) {
        int idx = it * 256 + tid;
        int row = idx >> 4;
        int k4  = (idx & 15) * 4;
        float4 v = *(const float4*)&hb[row * 64 + k4];
        __half* p = hs + row * 64 + (k4 ^ (8 * (row & 7)));
        *(half2*)p       = __floats2half2_rn(v.x, v.y);
        *(half2*)(p + 2) = __floats2half2_rn(v.z, v.w);
    }

    // ---------------- GEMM1 on tensor pipe: htt[o][row] = W^T @ h^T -----------
    // 4 passes (one per head / 64-o slice). Warp tile: 32 o x 32 rows.
    {
        const int ow = (wid & 1) * 32;     // o offset within slice
        const int rb = wid >> 1;           // row block (32 rows)
        const int swA = 8 * (lrow & 7);    // xor swizzle (same for o and o+16)

        #pragma unroll 1
        for (int p = 0; p < 4; p++) {
            if (p > 0) __syncthreads();    // pass p-1 frag reads done
            // Stage Wt[o'][k ^ 8*(o'&7)] = W[k][p*64+o'] fp16
            #pragma unroll
            for (int it = 0; it < 4; it++) {
                int idx = it * 256 + tid;
                int k   = idx >> 4;
                int o4  = (idx & 15) * 4;
                float4 v = *(const float4*)&Wg[k * 256 + p * 64 + o4];
                Wt[(o4 + 0) * 64 + (k ^ (8 * ((o4 + 0) & 7)))] = __float2half_rn(v.x);
                Wt[(o4 + 1) * 64 + (k ^ (8 * ((o4 + 1) & 7)))] = __float2half_rn(v.y);
                Wt[(o4 + 2) * 64 + (k ^ (8 * ((o4 + 2) & 7)))] = __float2half_rn(v.z);
                Wt[(o4 + 3) * 64 + (k ^ (8 * ((o4 + 3) & 7)))] = __float2half_rn(v.w);
            }
            __syncthreads();               // hs (first pass) + Wt visible

            float C[8][4];
            #pragma unroll
            for (int i = 0; i < 8; i++)
                #pragma unroll
                for (int q = 0; q < 4; q++) C[i][q] = 0.f;

            // per-lane ldmatrix base addresses (bytes)
            const uint32_t aA0 = wt_s + 2 * ((ow + lrow) * 64);
            const uint32_t aB0 = hs_s + 2 * ((rb * 32 + lrow) * 64);

            #pragma unroll
            for (int ks = 0; ks < 4; ks++) {
                const int chunk = ((ks * 16 + 8 * lhi) ^ swA) * 2;
                uint32_t A[2][4];
                ldm_x4(A[0][0], A[0][1], A[0][2], A[0][3], aA0 + chunk);
                ldm_x4(A[1][0], A[1][1], A[1][2], A[1][3], aA0 + 2 * (16 * 64) + chunk);
                #pragma unroll
                for (int np = 0; np < 2; np++) {
                    uint32_t r0, r1, r2, r3;
                    ldm_x4(r0, r1, r2, r3, aB0 + 2 * (np * 16 * 64) + chunk);
                    mma_f16(C[np * 2],     A[0][0], A[0][1], A[0][2], A[0][3], r0, r2);
                    mma_f16(C[np * 2 + 1], A[0][0], A[0][1], A[0][2], A[0][3], r1, r3);
                    mma_f16(C[4 + np * 2],     A[1][0], A[1][1], A[1][2], A[1][3], r0, r2);
                    mma_f16(C[4 + np * 2 + 1], A[1][0], A[1][1], A[1][2], A[1][3], r1, r3);
                }
            }

            // Store htt (half2, conflict-free)
            #pragma unroll
            for (int mt = 0; mt < 2; mt++) {
                #pragma unroll
                for (int nt = 0; nt < 4; nt++) {
                    const float* c = C[mt * 4 + nt];
                    const int o   = p * 64 + ow + mt * 16 + g;
                    const int row = rb * 32 + nt * 8 + 2 * t;
                    *(half2*)&htt[o * HTS + row] =
                        __floats2half2_rn(c[0], c[1]);
                    *(half2*)&htt[(o + 8) * HTS + row] =
                        __floats2half2_rn(c[2], c[3]);
                }
            }
        }
    }
    __syncthreads();   // htt complete

    // ---------------- src/tgt: exact fp32 dot over htt columns ----------------
    {
        const int head = wid >> 1;
        const int rb2  = wid & 1;
        const int rowoff = rb2 * 64 + 2 * lane;
        float s0 = 0.f, s1 = 0.f, t0 = 0.f, t1 = 0.f;
        #pragma unroll 8
        for (int o = 0; o < 64; o++) {
            half2 v = *(const half2*)&htt[(head * 64 + o) * HTS + rowoff];
            float2 f = __half22float2(v);
            float av = a_s[head * 128 + o];
            float bv = a_s[head * 128 + 64 + o];
            s0 = fmaf(f.x, av, s0); s1 = fmaf(f.y, av, s1);
            t0 = fmaf(f.x, bv, t0); t1 = fmaf(f.y, bv, t1);
        }
        float2 sv; sv.x = s0; sv.y = s1;
        float2 tv; tv.x = t0; tv.y = t1;
        *(float2*)&src_s[head * 128 + rowoff] = sv;
        *(float2*)&tgt_s[head * 128 + rowoff] = tv;
    }
    __syncthreads();   // src/tgt ready; hs/Wt dead -> attn region free

    // ---------------- Head loop: e-phase -> fp16 MMA GEMM2 --------------------
    const int kr   = wid >> 2;
    const int quad = wid & 3;
    const int r0q  = quad * 32;

    float C[16][4];
    #pragma unroll
    for (int i = 0; i < 16; i++)
        #pragma unroll
        for (int q = 0; q < 4; q++) C[i][q] = 0.f;

    #pragma unroll 1
    for (int h = 0; h < 4; h++) {
        // ---- e-phase: warp handles rows wid*16..+15; lane covers j=2L,2L+1 (+64) ----
        {
            const float* srch = src_s + h * 128;
            const float* tgth = tgt_s + h * 128;
            float2 tA = *(const float2*)&tgth[2 * lane];
            float2 tB = *(const float2*)&tgth[64 + 2 * lane];
            const int mw = lane >> 4;
            const int mb = 2 * (lane & 15);

            #pragma unroll 1
            for (int rr = 0; rr < 16; rr++) {
                const int i = wid * 16 + rr;
                const float si = srch[i];
                unsigned w0 = maskb[i * 4 + mw]     >> mb;
                unsigned w1 = maskb[i * 4 + 2 + mw] >> mb;
                float p[4];
                {
                    float sg = rcp_approx(1.0f + __expf(-(si + tA.x)));
                    p[0] = (w0 & 1u) ? 0.f : exp01(sg);
                }
                {
                    float sg = rcp_approx(1.0f + __expf(-(si + tA.y)));
                    p[1] = (w0 & 2u) ? 0.f : exp01(sg);
                }
                {
                    float sg = rcp_approx(1.0f + __expf(-(si + tB.x)));
                    p[2] = (w1 & 1u) ? 0.f : exp01(sg);
                }
                {
                    float sg = rcp_approx(1.0f + __expf(-(si + tB.y)));
                    p[3] = (w1 & 2u) ? 0.f : exp01(sg);
                }
                float rs = (p[0] + p[1]) + (p[2] + p[3]);
                #pragma unroll
                for (int m = 16; m >= 1; m >>= 1)
                    rs += __shfl_xor_sync(0xffffffffu, rs, m);
                const float inv = rcp_approx(rs);
                *(half2*)(attn_h + i * HTS + 2 * lane) =
                    __floats2half2_rn(p[0] * inv, p[1] * inv);
                *(half2*)(attn_h + i * HTS + 64 + 2 * lane) =
                    __floats2half2_rn(p[2] * inv, p[3] * inv);
            }
        }
        __syncthreads();

        // ---- GEMM2 slice (ldmatrix): C += attn[r0q.., kslice] @ htt[h*64.., kslice] ----
        {
            // per-lane ldmatrix base addresses
            const uint32_t aA0 = att_s + 2 * ((r0q + lrow) * HTS + 8 * lhi + kr * 64);
            const uint32_t aB0 = htt_s + 2 * (((h * 64) + lrow) * HTS + 8 * lhi + kr * 64);

            #pragma unroll
            for (int ks = 0; ks < 4; ks++) {
                const uint32_t koff = 2 * (ks * 16);
                uint32_t A[2][4];
                ldm_x4(A[0][0], A[0][1], A[0][2], A[0][3], aA0 + koff);
                ldm_x4(A[1][0], A[1][1], A[1][2], A[1][3],
                       aA0 + 2 * (16 * HTS) + koff);
                #pragma unroll
                for (int q = 0; q < 4; q++) {
                    uint32_t r0, r1, r2, r3;
                    ldm_x4(r0, r1, r2, r3, aB0 + 2 * (q * 16 * HTS) + koff);
                    mma_f16(C[2 * q],     A[0][0], A[0][1], A[0][2], A[0][3], r0, r2);
                    mma_f16(C[2 * q + 1], A[0][0], A[0][1], A[0][2], A[0][3], r1, r3);
                    mma_f16(C[8 + 2 * q],     A[1][0], A[1][1], A[1][2], A[1][3], r0, r2);
                    mma_f16(C[8 + 2 * q + 1], A[1][0], A[1][1], A[1][2], A[1][3], r1, r3);
                }
            }
        }
        __syncthreads();   // attn reused by next head
    }

    // ---------------- K-split reduction (stage in dead htt region) ------------
    // C tile index ti = mt*8 + gq covers rows r0q + mt*16 + {g, g+8? no: frag},
    // cols gq*8 + 2t (same mapping as before with nh*4+nt == gq).
    float* stage = (float*)smem_b;
    if (kr == 1) {
        float* buf = stage + quad * 2048;
        #pragma unroll
        for (int i = 0; i < 16; i++)
            #pragma unroll
            for (int q = 0; q < 4; q++)
                buf[(i * 4 + q) * 32 + lane] = C[i][q];
    }
    __syncthreads();

    if (kr == 0) {
        const float* buf = stage + quad * 2048;
        #pragma unroll
        for (int mt = 0; mt < 2; mt++) {
            #pragma unroll
            for (int gq = 0; gq < 8; gq++) {
                const int ti = mt * 8 + gq;
                float v0 = C[ti][0] + buf[(ti * 4 + 0) * 32 + lane];
                float v1 = C[ti][1] + buf[(ti * 4 + 1) * 32 + lane];
                float v2 = C[ti][2] + buf[(ti * 4 + 2) * 32 + lane];
                float v3 = C[ti][3] + buf[(ti * 4 + 3) * 32 + lane];
                const int row = r0q + mt * 16 + g;
                const int col = gq * 8 + 2 * t;
                float2 o0; o0.x = v0 * 0.25f; o0.y = v1 * 0.25f;
                float2 o1; o1.x = v2 * 0.25f; o1.y = v3 * 0.25f;
                *(float2*)&outb[row * 64 + col]       = o0;
                *(float2*)&outb[(row + 8) * 64 + col] = o1;
            }
        }
    }
}

extern "C" void kernel_launch(void* const* d_in, const int* in_sizes, int n_in,
                              void* d_out, int out_size)
{
    const float* h   = (const float*)d_in[0];
    const float* adj = (const float*)d_in[1];
    const float* W   = (const float*)d_in[2];
    const float* a   = (const float*)d_in[3];
    float* out = (float*)d_out;

    static bool attr_set = false;
    if (!attr_set) {
        cudaFuncSetAttribute(gat_fused_kernel,
                             cudaFuncAttributeMaxDynamicSharedMemorySize,
                             SMEM_BYTES);
        attr_set = true;
    }

    gat_fused_kernel<<<BATCH_SEQ, THREADS, SMEM_BYTES>>>(h, adj, W, a, out);
}

// round 10
// speedup vs baseline: 2.8441x; 1.0640x over previous
#include <cuda_runtime.h>
#include <cuda_fp16.h>
#include <cstdint>

// Problem constants
#define BATCH_SEQ 640          // B*S = 32*20
#define THREADS   256
#define ADJ_THR   0.05f

__device__ __forceinline__ float rcp_approx(float x) {
    float r; asm("rcp.approx.f32 %0, %1;" : "=f"(r) : "f"(x)); return r;
}
// e^y for y in [0,1]: degree-7 Taylor (max rel err ~2.8e-5)
__device__ __forceinline__ float exp01(float y) {
    float p = 1.9841270e-4f;
    p = fmaf(p, y, 1.3888889e-3f);
    p = fmaf(p, y, 8.3333333e-3f);
    p = fmaf(p, y, 4.1666668e-2f);
    p = fmaf(p, y, 1.6666667e-1f);
    p = fmaf(p, y, 0.5f);
    p = fmaf(p, y, 1.0f);
    p = fmaf(p, y, 1.0f);
    return p;
}
// fp16 mma m16n8k16, fp32 accum
__device__ __forceinline__ void mma_f16(float c[4],
                                        uint32_t a0, uint32_t a1, uint32_t a2, uint32_t a3,
                                        uint32_t b0, uint32_t b1) {
    asm volatile("mma.sync.aligned.m16n8k16.row.col.f32.f16.f16.f32 "
                 "{%0,%1,%2,%3}, {%4,%5,%6,%7}, {%8,%9}, {%0,%1,%2,%3};"
                 : "+f"(c[0]), "+f"(c[1]), "+f"(c[2]), "+f"(c[3])
                 : "r"(a0), "r"(a1), "r"(a2), "r"(a3), "r"(b0), "r"(b1));
}
__device__ __forceinline__ uint32_t cvta_s(const void* p) {
    uint32_t a; asm("{ .reg .u64 t; cvta.to.shared.u64 t, %1; cvt.u32.u64 %0, t; }"
                    : "=r"(a) : "l"(p));
    return a;
}
__device__ __forceinline__ void ldm_x4(uint32_t& r0, uint32_t& r1,
                                       uint32_t& r2, uint32_t& r3, uint32_t a) {
    asm volatile("ldmatrix.sync.aligned.m8n8.x4.shared.b16 {%0,%1,%2,%3}, [%4];"
                 : "=r"(r0), "=r"(r1), "=r"(r2), "=r"(r3) : "r"(a));
}

// Shared memory layout (bytes) — ONE head resident at a time:
//   hs   [128 row][64 k] fp16 XOR-swz @ 0      (16384)
//   htt  [64 o][136 k-halves] fp16    @ 16384  (17408)  current head's ht^T
//   ATT  @ 33792 (34816):
//     GEMM1 phase: Wt [64 o'][64 k] fp16 XOR-swz
//     attn phase : attn [128 i][136 k] fp16
//   src_s [128] f32  @ 68608 (512)
//   tgt_s [128] f32  @ 69120 (512)
//   maskb [512] u32  @ 69632 (2048)
//   a_s   [512] f32  @ 71680 (2048)
// total 73728 B -> 3 CTAs/SM (221184 <= 228KB)
#define HTS       136
#define HTT_OFF   16384
#define ATT_OFF   33792
#define SRC_OFF   68608
#define TGT_OFF   69120
#define MSK_OFF   69632
#define AS_OFF    71680
#define SMEM_BYTES 73728

extern __shared__ char smem_b[];

__global__ __launch_bounds__(THREADS, 3)
void gat_fused_kernel(const float* __restrict__ hg,
                      const float* __restrict__ adjg,
                      const float* __restrict__ Wg,
                      const float* __restrict__ ag,
                      float* __restrict__ outg)
{
    __half* hs     = (__half*)smem_b;
    __half* htt    = (__half*)(smem_b + HTT_OFF);
    __half* attn_h = (__half*)(smem_b + ATT_OFF);
    __half* Wt     = (__half*)(smem_b + ATT_OFF);   // union with attn
    float*  src_s  = (float*)(smem_b + SRC_OFF);
    float*  tgt_s  = (float*)(smem_b + TGT_OFF);
    unsigned* maskb = (unsigned*)(smem_b + MSK_OFF);
    float*  a_s    = (float*)(smem_b + AS_OFF);

    const int tid  = threadIdx.x;
    const int lane = tid & 31;
    const int wid  = tid >> 5;      // 0..7
    const int g    = lane >> 2;     // 0..7
    const int t    = lane & 3;      // 0..3
    const int lrow = lane & 15;
    const int lhi  = lane >> 4;
    const int bs   = blockIdx.x;

    const float* hb   = hg   + (size_t)bs * 128 * 64;
    const float* adjb = adjg + (size_t)bs * 128 * 128;
    float*       outb = outg + (size_t)bs * 128 * 64;

    const uint32_t hs_s  = cvta_s(hs);
    const uint32_t htt_s = cvta_s(htt);
    const uint32_t att_s = cvta_s(attn_h);
    const uint32_t wt_s  = att_s;

    // ---------------- Prologue: a_s, adjacency bitmask, hs (fp16 h) -----------
    a_s[tid]       = ag[tid];
    a_s[256 + tid] = ag[256 + tid];

    #pragma unroll 8
    for (int it = 0; it < 64; it++) {
        int idx = it * 256 + tid;
        unsigned bal = __ballot_sync(0xffffffffu, adjb[idx] < ADJ_THR);
        if (lane == 0) maskb[idx >> 5] = bal;
    }

    // hs[row][k ^ 8*(row&7)] fp16
    #pragma unroll
    for (int it = 0; it < 8; it++) {
        int idx = it * 256 + tid;
        int row = idx >> 4;
        int k4  = (idx & 15) * 4;
        float4 v = *(const float4*)&hb[row * 64 + k4];
        __half* p = hs + row * 64 + (k4 ^ (8 * (row & 7)));
        *(half2*)p       = __floats2half2_rn(v.x, v.y);
        *(half2*)(p + 2) = __floats2half2_rn(v.z, v.w);
    }

    // GEMM2 accumulator: warp rows wid*16..+15, all 64 cols, full K, all heads
    float C[8][4];
    #pragma unroll
    for (int i = 0; i < 8; i++)
        #pragma unroll
        for (int q = 0; q < 4; q++) C[i][q] = 0.f;

    // ================== Per-head pipeline ==================
    #pragma unroll 1
    for (int h = 0; h < 4; h++) {
        __syncthreads();   // prev GEMM2 attn reads done (or prologue hs done)

        // ---- Stage Wt[o'][k ^ 8*(o'&7)] = W[k][h*64+o'] fp16 ----
        #pragma unroll
        for (int it = 0; it < 4; it++) {
            int idx = it * 256 + tid;
            int k   = idx >> 4;
            int o4  = (idx & 15) * 4;
            float4 v = *(const float4*)&Wg[k * 256 + h * 64 + o4];
            Wt[(o4 + 0) * 64 + (k ^ (8 * ((o4 + 0) & 7)))] = __float2half_rn(v.x);
            Wt[(o4 + 1) * 64 + (k ^ (8 * ((o4 + 1) & 7)))] = __float2half_rn(v.y);
            Wt[(o4 + 2) * 64 + (k ^ (8 * ((o4 + 2) & 7)))] = __float2half_rn(v.z);
            Wt[(o4 + 3) * 64 + (k ^ (8 * ((o4 + 3) & 7)))] = __float2half_rn(v.w);
        }
        __syncthreads();

        // ---- GEMM1: htt[o][row] = Wt_h^T @ h^T ; warp tile 16 o x 64 rows ----
        {
            const int ob = (wid >> 1) * 16;   // o block
            const int rb = wid & 1;           // row half (64 rows)
            const uint32_t aA0 = wt_s + 2 * ((ob + lrow) * 64);
            const uint32_t aB0 = hs_s + 2 * ((rb * 64 + lrow) * 64);

            #pragma unroll
            for (int qh = 0; qh < 2; qh++) {
                float D[4][4];
                #pragma unroll
                for (int i = 0; i < 4; i++)
                    #pragma unroll
                    for (int q = 0; q < 4; q++) D[i][q] = 0.f;

                #pragma unroll
                for (int ks = 0; ks < 4; ks++) {
                    const int chunk = ((ks * 16 + 8 * lhi) ^ (8 * (lrow & 7))) * 2;
                    uint32_t A0, A1, A2, A3;
                    ldm_x4(A0, A1, A2, A3, aA0 + chunk);
                    #pragma unroll
                    for (int q2 = 0; q2 < 2; q2++) {
                        const int q = qh * 2 + q2;
                        uint32_t r0, r1, r2, r3;
                        ldm_x4(r0, r1, r2, r3, aB0 + 2 * (q * 16 * 64) + chunk);
                        mma_f16(D[2 * q2],     A0, A1, A2, A3, r0, r2);
                        mma_f16(D[2 * q2 + 1], A0, A1, A2, A3, r1, r3);
                    }
                }
                // store htt (half2, conflict-free)
                #pragma unroll
                for (int q2 = 0; q2 < 2; q2++) {
                    #pragma unroll
                    for (int j = 0; j < 2; j++) {
                        const float* c = D[2 * q2 + j];
                        const int row = rb * 64 + (qh * 2 + q2) * 16 + j * 8 + 2 * t;
                        *(half2*)&htt[(ob + g) * HTS + row] =
                            __floats2half2_rn(c[0], c[1]);
                        *(half2*)&htt[(ob + g + 8) * HTS + row] =
                            __floats2half2_rn(c[2], c[3]);
                    }
                }
            }
        }
        __syncthreads();   // htt visible

        // ---- src/tgt: exact fp32 dots over htt columns ----
        {
            const int rr2 = 2 * (lane & 7);
            const int oc  = lane >> 3;          // o-chunk (16 o's)
            const int row = wid * 16 + rr2;
            float s0 = 0.f, s1 = 0.f, t0 = 0.f, t1 = 0.f;
            #pragma unroll 8
            for (int o4 = 0; o4 < 16; o4++) {
                const int o = oc * 16 + o4;
                float2 f = __half22float2(*(const half2*)&htt[o * HTS + row]);
                float av = a_s[h * 128 + o];
                float bv = a_s[h * 128 + 64 + o];
                s0 = fmaf(f.x, av, s0); s1 = fmaf(f.y, av, s1);
                t0 = fmaf(f.x, bv, t0); t1 = fmaf(f.y, bv, t1);
            }
            #pragma unroll
            for (int m = 8; m <= 16; m <<= 1) {
                s0 += __shfl_xor_sync(0xffffffffu, s0, m);
                s1 += __shfl_xor_sync(0xffffffffu, s1, m);
                t0 += __shfl_xor_sync(0xffffffffu, t0, m);
                t1 += __shfl_xor_sync(0xffffffffu, t1, m);
            }
            if (lane < 8) {
                float2 sv; sv.x = s0; sv.y = s1;
                float2 tv; tv.x = t0; tv.y = t1;
                *(float2*)&src_s[row] = sv;
                *(float2*)&tgt_s[row] = tv;
            }
        }
        __syncthreads();   // src/tgt ready; Wt dead -> attn region free

        // ---- e-phase: rows wid*16..+15; lane covers j=2L,2L+1 (+64) ----
        {
            float2 tA = *(const float2*)&tgt_s[2 * lane];
            float2 tB = *(const float2*)&tgt_s[64 + 2 * lane];
            const int mw = lane >> 4;
            const int mb = 2 * (lane & 15);

            #pragma unroll 1
            for (int rr = 0; rr < 16; rr++) {
                const int i = wid * 16 + rr;
                const float si = src_s[i];
                unsigned w0 = maskb[i * 4 + mw]     >> mb;
                unsigned w1 = maskb[i * 4 + 2 + mw] >> mb;
                float p[4];
                {
                    float sg = rcp_approx(1.0f + __expf(-(si + tA.x)));
                    p[0] = (w0 & 1u) ? 0.f : exp01(sg);
                }
                {
                    float sg = rcp_approx(1.0f + __expf(-(si + tA.y)));
                    p[1] = (w0 & 2u) ? 0.f : exp01(sg);
                }
                {
                    float sg = rcp_approx(1.0f + __expf(-(si + tB.x)));
                    p[2] = (w1 & 1u) ? 0.f : exp01(sg);
                }
                {
                    float sg = rcp_approx(1.0f + __expf(-(si + tB.y)));
                    p[3] = (w1 & 2u) ? 0.f : exp01(sg);
                }
                float rs = (p[0] + p[1]) + (p[2] + p[3]);
                #pragma unroll
                for (int m = 16; m >= 1; m >>= 1)
                    rs += __shfl_xor_sync(0xffffffffu, rs, m);
                const float inv = rcp_approx(rs);
                *(half2*)(attn_h + i * HTS + 2 * lane) =
                    __floats2half2_rn(p[0] * inv, p[1] * inv);
                *(half2*)(attn_h + i * HTS + 64 + 2 * lane) =
                    __floats2half2_rn(p[2] * inv, p[3] * inv);
            }
        }
        __syncthreads();

        // ---- GEMM2: C += attn[wid*16.., :] @ htt[:, :]  (full K=128) ----
        {
            const uint32_t aA0 = att_s + 2 * ((wid * 16 + lrow) * HTS + 8 * lhi);
            const uint32_t aB0 = htt_s + 2 * (lrow * HTS + 8 * lhi);

            #pragma unroll
            for (int ks = 0; ks < 8; ks++) {
                const uint32_t koff = 2 * (16 * ks);
                uint32_t A0, A1, A2, A3;
                ldm_x4(A0, A1, A2, A3, aA0 + koff);
                #pragma unroll
                for (int q = 0; q < 4; q++) {
                    uint32_t r0, r1, r2, r3;
                    ldm_x4(r0, r1, r2, r3, aB0 + 2 * (q * 16 * HTS) + koff);
                    mma_f16(C[2 * q],     A0, A1, A2, A3, r0, r2);
                    mma_f16(C[2 * q + 1], A0, A1, A2, A3, r1, r3);
                }
            }
        }
        // loop-top __syncthreads() protects attn before next Wt stage
    }

    // ---------------- Epilogue: C holds full output rows; mean over heads -----
    #pragma unroll
    for (int ti = 0; ti < 8; ti++) {
        const int row = wid * 16 + g;
        const int col = ti * 8 + 2 * t;
        float2 o0; o0.x = C[ti][0] * 0.25f; o0.y = C[ti][1] * 0.25f;
        float2 o1; o1.x = C[ti][2] * 0.25f; o1.y = C[ti][3] * 0.25f;
        *(float2*)&outb[row * 64 + col]       = o0;
        *(float2*)&outb[(row + 8) * 64 + col] = o1;
    }
}

extern "C" void kernel_launch(void* const* d_in, const int* in_sizes, int n_in,
                              void* d_out, int out_size)
{
    const float* h   = (const float*)d_in[0];
    const float* adj = (const float*)d_in[1];
    const float* W   = (const float*)d_in[2];
    const float* a   = (const float*)d_in[3];
    float* out = (float*)d_out;

    static bool attr_set = false;
    if (!attr_set) {
        cudaFuncSetAttribute(gat_fused_kernel,
                             cudaFuncAttributeMaxDynamicSharedMemorySize,
                             SMEM_BYTES);
        attr_set = true;
    }

    gat_fused_kernel<<<BATCH_SEQ, THREADS, SMEM_BYTES>>>(h, adj, W, a, out);
}

// round 11
// speedup vs baseline: 3.3669x; 1.1838x over previous
#include <cuda_runtime.h>
#include <cuda_fp16.h>
#include <cstdint>

// Problem constants
#define BATCH_SEQ 640          // B*S = 32*20
#define THREADS   256
#define ADJ_THR   0.05f

__device__ __forceinline__ float rcp_approx(float x) {
    float r; asm("rcp.approx.f32 %0, %1;" : "=f"(r) : "f"(x)); return r;
}
__device__ __forceinline__ float tanh_apx(float x) {
    float r; asm("tanh.approx.f32 %0, %1;" : "=f"(r) : "f"(x)); return r;
}
__device__ __forceinline__ float ex2_apx(float x) {
    float r; asm("ex2.approx.f32 %0, %1;" : "=f"(r) : "f"(x)); return r;
}
// exp(sigmoid(x)) given xh = x/2:  exp(0.5*tanh(xh)+0.5) = 2^(c*tanh(xh)+c)
#define EXP_SIG_C 0.72134752044f   // log2(e)/2
__device__ __forceinline__ float exp_sigmoid_half(float xh) {
    return ex2_apx(fmaf(EXP_SIG_C, tanh_apx(xh), EXP_SIG_C));
}
// fp16 mma m16n8k16, fp32 accum
__device__ __forceinline__ void mma_f16(float c[4],
                                        uint32_t a0, uint32_t a1, uint32_t a2, uint32_t a3,
                                        uint32_t b0, uint32_t b1) {
    asm volatile("mma.sync.aligned.m16n8k16.row.col.f32.f16.f16.f32 "
                 "{%0,%1,%2,%3}, {%4,%5,%6,%7}, {%8,%9}, {%0,%1,%2,%3};"
                 : "+f"(c[0]), "+f"(c[1]), "+f"(c[2]), "+f"(c[3])
                 : "r"(a0), "r"(a1), "r"(a2), "r"(a3), "r"(b0), "r"(b1));
}
__device__ __forceinline__ uint32_t cvta_s(const void* p) {
    uint32_t a; asm("{ .reg .u64 t; cvta.to.shared.u64 t, %1; cvt.u32.u64 %0, t; }"
                    : "=r"(a) : "l"(p));
    return a;
}
__device__ __forceinline__ void ldm_x4(uint32_t& r0, uint32_t& r1,
                                       uint32_t& r2, uint32_t& r3, uint32_t a) {
    asm volatile("ldmatrix.sync.aligned.m8n8.x4.shared.b16 {%0,%1,%2,%3}, [%4];"
                 : "=r"(r0), "=r"(r1), "=r"(r2), "=r"(r3) : "r"(a));
}

// Shared memory layout (bytes) — ONE head resident at a time:
//   hs   [128 row][64 k] fp16 XOR-swz @ 0      (16384)
//   htt  [64 o][136 k-halves] fp16    @ 16384  (17408)  current head's ht^T
//   ATT  @ 33792 (34816):
//     GEMM1 phase: Wt [64 o'][64 k] fp16 XOR-swz
//     attn phase : attn [128 i][136 k] fp16
//   src_s [128] f32  @ 68608 (512)
//   tgt_s [128] f32  @ 69120 (512)
//   maskb [512] u32  @ 69632 (2048)
//   a_s   [512] f32  @ 71680 (2048)
// total 73728 B -> 3 CTAs/SM
#define HTS       136
#define HTT_OFF   16384
#define ATT_OFF   33792
#define SRC_OFF   68608
#define TGT_OFF   69120
#define MSK_OFF   69632
#define AS_OFF    71680
#define SMEM_BYTES 73728

extern __shared__ char smem_b[];

__global__ __launch_bounds__(THREADS, 3)
void gat_fused_kernel(const float* __restrict__ hg,
                      const float* __restrict__ adjg,
                      const float* __restrict__ Wg,
                      const float* __restrict__ ag,
                      float* __restrict__ outg)
{
    __half* hs     = (__half*)smem_b;
    __half* htt    = (__half*)(smem_b + HTT_OFF);
    __half* attn_h = (__half*)(smem_b + ATT_OFF);
    __half* Wt     = (__half*)(smem_b + ATT_OFF);   // union with attn
    float*  src_s  = (float*)(smem_b + SRC_OFF);
    float*  tgt_s  = (float*)(smem_b + TGT_OFF);
    unsigned* maskb = (unsigned*)(smem_b + MSK_OFF);
    float*  a_s    = (float*)(smem_b + AS_OFF);

    const int tid  = threadIdx.x;
    const int lane = tid & 31;
    const int wid  = tid >> 5;      // 0..7
    const int g    = lane >> 2;     // 0..7
    const int t    = lane & 3;      // 0..3
    const int lrow = lane & 15;
    const int lhi  = lane >> 4;
    const int bs   = blockIdx.x;

    const float* hb   = hg   + (size_t)bs * 128 * 64;
    const float* adjb = adjg + (size_t)bs * 128 * 128;
    float*       outb = outg + (size_t)bs * 128 * 64;

    const uint32_t hs_s  = cvta_s(hs);
    const uint32_t htt_s = cvta_s(htt);
    const uint32_t att_s = cvta_s(attn_h);
    const uint32_t wt_s  = att_s;

    // ---------------- Prologue: a_s, adjacency bitmask, hs (fp16 h) -----------
    a_s[tid]       = ag[tid];
    a_s[256 + tid] = ag[256 + tid];

    #pragma unroll 8
    for (int it = 0; it < 64; it++) {
        int idx = it * 256 + tid;
        unsigned bal = __ballot_sync(0xffffffffu, adjb[idx] < ADJ_THR);
        if (lane == 0) maskb[idx >> 5] = bal;
    }

    // hs[row][k ^ 8*(row&7)] fp16
    #pragma unroll
    for (int it = 0; it < 8; it++) {
        int idx = it * 256 + tid;
        int row = idx >> 4;
        int k4  = (idx & 15) * 4;
        float4 v = *(const float4*)&hb[row * 64 + k4];
        __half* p = hs + row * 64 + (k4 ^ (8 * (row & 7)));
        *(half2*)p       = __floats2half2_rn(v.x, v.y);
        *(half2*)(p + 2) = __floats2half2_rn(v.z, v.w);
    }

    // GEMM2 accumulator: warp rows wid*16..+15, all 64 cols, full K, all heads
    float C[8][4];
    #pragma unroll
    for (int i = 0; i < 8; i++)
        #pragma unroll
        for (int q = 0; q < 4; q++) C[i][q] = 0.f;

    // ================== Per-head pipeline ==================
    #pragma unroll 1
    for (int h = 0; h < 4; h++) {
        __syncthreads();   // prev GEMM2 attn reads done (or prologue hs done)

        // ---- Stage Wt[o'][k ^ 8*(o'&7)] = W[k][h*64+o'] fp16 ----
        #pragma unroll
        for (int it = 0; it < 4; it++) {
            int idx = it * 256 + tid;
            int k   = idx >> 4;
            int o4  = (idx & 15) * 4;
            float4 v = *(const float4*)&Wg[k * 256 + h * 64 + o4];
            Wt[(o4 + 0) * 64 + (k ^ (8 * ((o4 + 0) & 7)))] = __float2half_rn(v.x);
            Wt[(o4 + 1) * 64 + (k ^ (8 * ((o4 + 1) & 7)))] = __float2half_rn(v.y);
            Wt[(o4 + 2) * 64 + (k ^ (8 * ((o4 + 2) & 7)))] = __float2half_rn(v.z);
            Wt[(o4 + 3) * 64 + (k ^ (8 * ((o4 + 3) & 7)))] = __float2half_rn(v.w);
        }
        __syncthreads();

        // ---- GEMM1: htt[o][row] = Wt_h^T @ h^T ; warp tile 16 o x 64 rows ----
        {
            const int ob = (wid >> 1) * 16;   // o block
            const int rb = wid & 1;           // row half (64 rows)
            const uint32_t aA0 = wt_s + 2 * ((ob + lrow) * 64);
            const uint32_t aB0 = hs_s + 2 * ((rb * 64 + lrow) * 64);

            #pragma unroll
            for (int qh = 0; qh < 2; qh++) {
                float D[4][4];
                #pragma unroll
                for (int i = 0; i < 4; i++)
                    #pragma unroll
                    for (int q = 0; q < 4; q++) D[i][q] = 0.f;

                #pragma unroll
                for (int ks = 0; ks < 4; ks++) {
                    const int chunk = ((ks * 16 + 8 * lhi) ^ (8 * (lrow & 7))) * 2;
                    uint32_t A0, A1, A2, A3;
                    ldm_x4(A0, A1, A2, A3, aA0 + chunk);
                    #pragma unroll
                    for (int q2 = 0; q2 < 2; q2++) {
                        const int q = qh * 2 + q2;
                        uint32_t r0, r1, r2, r3;
                        ldm_x4(r0, r1, r2, r3, aB0 + 2 * (q * 16 * 64) + chunk);
                        mma_f16(D[2 * q2],     A0, A1, A2, A3, r0, r2);
                        mma_f16(D[2 * q2 + 1], A0, A1, A2, A3, r1, r3);
                    }
                }
                // store htt (half2, conflict-free)
                #pragma unroll
                for (int q2 = 0; q2 < 2; q2++) {
                    #pragma unroll
                    for (int j = 0; j < 2; j++) {
                        const float* c = D[2 * q2 + j];
                        const int row = rb * 64 + (qh * 2 + q2) * 16 + j * 8 + 2 * t;
                        *(half2*)&htt[(ob + g) * HTS + row] =
                            __floats2half2_rn(c[0], c[1]);
                        *(half2*)&htt[(ob + g + 8) * HTS + row] =
                            __floats2half2_rn(c[2], c[3]);
                    }
                }
            }
        }
        __syncthreads();   // htt visible

        // ---- src/tgt: exact fp32 dots over htt columns ----
        {
            const int rr2 = 2 * (lane & 7);
            const int oc  = lane >> 3;          // o-chunk (16 o's)
            const int row = wid * 16 + rr2;
            float s0 = 0.f, s1 = 0.f, t0 = 0.f, t1 = 0.f;
            #pragma unroll 8
            for (int o4 = 0; o4 < 16; o4++) {
                const int o = oc * 16 + o4;
                float2 f = __half22float2(*(const half2*)&htt[o * HTS + row]);
                float av = a_s[h * 128 + o];
                float bv = a_s[h * 128 + 64 + o];
                s0 = fmaf(f.x, av, s0); s1 = fmaf(f.y, av, s1);
                t0 = fmaf(f.x, bv, t0); t1 = fmaf(f.y, bv, t1);
            }
            #pragma unroll
            for (int m = 8; m <= 16; m <<= 1) {
                s0 += __shfl_xor_sync(0xffffffffu, s0, m);
                s1 += __shfl_xor_sync(0xffffffffu, s1, m);
                t0 += __shfl_xor_sync(0xffffffffu, t0, m);
                t1 += __shfl_xor_sync(0xffffffffu, t1, m);
            }
            if (lane < 8) {
                float2 sv; sv.x = s0; sv.y = s1;
                float2 tv; tv.x = t0; tv.y = t1;
                *(float2*)&src_s[row] = sv;
                *(float2*)&tgt_s[row] = tv;
            }
        }
        __syncthreads();   // src/tgt ready; Wt dead -> attn region free

        // ---- e-phase: rows wid*16..+15; lane covers j=2L,2L+1 (+64) ----
        // p = exp(sigmoid(si + tj)) = 2^(c*tanh((si+tj)/2) + c) : 5 issues/elem
        {
            float2 tA = *(const float2*)&tgt_s[2 * lane];
            float2 tB = *(const float2*)&tgt_s[64 + 2 * lane];
            // pre-halved target terms
            const float tA0 = 0.5f * tA.x, tA1 = 0.5f * tA.y;
            const float tB0 = 0.5f * tB.x, tB1 = 0.5f * tB.y;
            const int mw = lane >> 4;
            const int mb = 2 * (lane & 15);

            #pragma unroll 2
            for (int rr = 0; rr < 16; rr++) {
                const int i = wid * 16 + rr;
                const float sih = 0.5f * src_s[i];
                unsigned w0 = maskb[i * 4 + mw]     >> mb;
                unsigned w1 = maskb[i * 4 + 2 + mw] >> mb;
                float p0 = exp_sigmoid_half(sih + tA0);
                float p1 = exp_sigmoid_half(sih + tA1);
                float p2 = exp_sigmoid_half(sih + tB0);
                float p3 = exp_sigmoid_half(sih + tB1);
                if (w0 & 1u) p0 = 0.f;
                if (w0 & 2u) p1 = 0.f;
                if (w1 & 1u) p2 = 0.f;
                if (w1 & 2u) p3 = 0.f;
                float rs = (p0 + p1) + (p2 + p3);
                #pragma unroll
                for (int m = 16; m >= 1; m >>= 1)
                    rs += __shfl_xor_sync(0xffffffffu, rs, m);
                const float inv = rcp_approx(rs);
                *(half2*)(attn_h + i * HTS + 2 * lane) =
                    __floats2half2_rn(p0 * inv, p1 * inv);
                *(half2*)(attn_h + i * HTS + 64 + 2 * lane) =
                    __floats2half2_rn(p2 * inv, p3 * inv);
            }
        }
        __syncthreads();

        // ---- GEMM2: C += attn[wid*16.., :] @ htt[:, :]  (full K=128) ----
        {
            const uint32_t aA0 = att_s + 2 * ((wid * 16 + lrow) * HTS + 8 * lhi);
            const uint32_t aB0 = htt_s + 2 * (lrow * HTS + 8 * lhi);

            #pragma unroll
            for (int ks = 0; ks < 8; ks++) {
                const uint32_t koff = 2 * (16 * ks);
                uint32_t A0, A1, A2, A3;
                ldm_x4(A0, A1, A2, A3, aA0 + koff);
                #pragma unroll
                for (int q = 0; q < 4; q++) {
                    uint32_t r0, r1, r2, r3;
                    ldm_x4(r0, r1, r2, r3, aB0 + 2 * (q * 16 * HTS) + koff);
                    mma_f16(C[2 * q],     A0, A1, A2, A3, r0, r2);
                    mma_f16(C[2 * q + 1], A0, A1, A2, A3, r1, r3);
                }
            }
        }
        // loop-top __syncthreads() protects attn before next Wt stage
    }

    // ---------------- Epilogue: C holds full output rows; mean over heads -----
    #pragma unroll
    for (int ti = 0; ti < 8; ti++) {
        const int row = wid * 16 + g;
        const int col = ti * 8 + 2 * t;
        float2 o0; o0.x = C[ti][0] * 0.25f; o0.y = C[ti][1] * 0.25f;
        float2 o1; o1.x = C[ti][2] * 0.25f; o1.y = C[ti][3] * 0.25f;
        *(float2*)&outb[row * 64 + col]       = o0;
        *(float2*)&outb[(row + 8) * 64 + col] = o1;
    }
}

extern "C" void kernel_launch(void* const* d_in, const int* in_sizes, int n_in,
                              void* d_out, int out_size)
{
    const float* h   = (const float*)d_in[0];
    const float* adj = (const float*)d_in[1];
    const float* W   = (const float*)d_in[2];
    const float* a   = (const float*)d_in[3];
    float* out = (float*)d_out;

    static bool attr_set = false;
    if (!attr_set) {
        cudaFuncSetAttribute(gat_fused_kernel,
                             cudaFuncAttributeMaxDynamicSharedMemorySize,
                             SMEM_BYTES);
        attr_set = true;
    }

    gat_fused_kernel<<<BATCH_SEQ, THREADS, SMEM_BYTES>>>(h, adj, W, a, out);
}

// round 13
// speedup vs baseline: 3.8092x; 1.1314x over previous
#include <cuda_runtime.h>
#include <cuda_fp16.h>
#include <cstdint>

// Problem constants
#define BATCH_SEQ 640          // B*S = 32*20
#define THREADS   256
#define ADJ_THR   0.05f

__device__ __forceinline__ float rcp_approx(float x) {
    float r; asm("rcp.approx.f32 %0, %1;" : "=f"(r) : "f"(x)); return r;
}
__device__ __forceinline__ float tanh_apx(float x) {
    float r; asm("tanh.approx.f32 %0, %1;" : "=f"(r) : "f"(x)); return r;
}
__device__ __forceinline__ float ex2_apx(float x) {
    float r; asm("ex2.approx.f32 %0, %1;" : "=f"(r) : "f"(x)); return r;
}
// exp(sigmoid(x)) given xh = x/2:  exp(0.5*tanh(xh)+0.5) = 2^(c*tanh(xh)+c)
#define EXP_SIG_C 0.72134752044f   // log2(e)/2
__device__ __forceinline__ float exp_sigmoid_half(float xh) {
    return ex2_apx(fmaf(EXP_SIG_C, tanh_apx(xh), EXP_SIG_C));
}
// fp16 mma m16n8k16, fp32 accum
__device__ __forceinline__ void mma_f16(float c[4],
                                        uint32_t a0, uint32_t a1, uint32_t a2, uint32_t a3,
                                        uint32_t b0, uint32_t b1) {
    asm volatile("mma.sync.aligned.m16n8k16.row.col.f32.f16.f16.f32 "
                 "{%0,%1,%2,%3}, {%4,%5,%6,%7}, {%8,%9}, {%0,%1,%2,%3};"
                 : "+f"(c[0]), "+f"(c[1]), "+f"(c[2]), "+f"(c[3])
                 : "r"(a0), "r"(a1), "r"(a2), "r"(a3), "r"(b0), "r"(b1));
}
__device__ __forceinline__ uint32_t cvta_s(const void* p) {
    uint32_t a; asm("{ .reg .u64 t; cvta.to.shared.u64 t, %1; cvt.u32.u64 %0, t; }"
                    : "=r"(a) : "l"(p));
    return a;
}
__device__ __forceinline__ void ldm_x4(uint32_t& r0, uint32_t& r1,
                                       uint32_t& r2, uint32_t& r3, uint32_t a) {
    asm volatile("ldmatrix.sync.aligned.m8n8.x4.shared.b16 {%0,%1,%2,%3}, [%4];"
                 : "=r"(r0), "=r"(r1), "=r"(r2), "=r"(r3) : "r"(a));
}
__device__ __forceinline__ void ldm_x4_t(uint32_t& r0, uint32_t& r1,
                                         uint32_t& r2, uint32_t& r3, uint32_t a) {
    asm volatile("ldmatrix.sync.aligned.m8n8.x4.trans.shared.b16 {%0,%1,%2,%3}, [%4];"
                 : "=r"(r0), "=r"(r1), "=r"(r2), "=r"(r3) : "r"(a));
}

// Shared memory layout (bytes) — ONE head resident at a time:
//   hs   [128 row][64 k] fp16 XOR-swz @ 0      (16384)
//   htt  [64 o][136 k-halves] fp16    @ 16384  (17408)  current head's ht^T
//   ATT  @ 33792 (34816):
//     GEMM1 phase: Wtk [64 k][64 o] fp16, o XOR-swz by k  (8192)
//     attn phase : attn [128 i][136 k] fp16
//   src_s [128] f32  @ 68608 (512)
//   tgt_s [128] f32  @ 69120 (512)
//   maskb [512] u32  @ 69632 (2048)
//   a_s   [512] f32  @ 71680 (2048)
// total 73728 B -> 3 CTAs/SM
#define HTS       136
#define HTT_OFF   16384
#define ATT_OFF   33792
#define SRC_OFF   68608
#define TGT_OFF   69120
#define MSK_OFF   69632
#define AS_OFF    71680
#define SMEM_BYTES 73728

extern __shared__ char smem_b[];

__global__ __launch_bounds__(THREADS, 3)
void gat_fused_kernel(const float* __restrict__ hg,
                      const float* __restrict__ adjg,
                      const float* __restrict__ Wg,
                      const float* __restrict__ ag,
                      float* __restrict__ outg)
{
    __half* hs     = (__half*)smem_b;
    __half* htt    = (__half*)(smem_b + HTT_OFF);
    __half* attn_h = (__half*)(smem_b + ATT_OFF);
    __half* Wtk    = (__half*)(smem_b + ATT_OFF);   // union with attn
    float*  src_s  = (float*)(smem_b + SRC_OFF);
    float*  tgt_s  = (float*)(smem_b + TGT_OFF);
    unsigned* maskb = (unsigned*)(smem_b + MSK_OFF);
    float*  a_s    = (float*)(smem_b + AS_OFF);

    const int tid  = threadIdx.x;
    const int lane = tid & 31;
    const int wid  = tid >> 5;      // 0..7
    const int g    = lane >> 2;     // 0..7
    const int t    = lane & 3;      // 0..3
    const int lrow = lane & 15;
    const int lhi  = lane >> 4;
    const int bs   = blockIdx.x;

    const float* hb   = hg   + (size_t)bs * 128 * 64;
    const float* adjb = adjg + (size_t)bs * 128 * 128;
    float*       outb = outg + (size_t)bs * 128 * 64;

    const uint32_t hs_s  = cvta_s(hs);
    const uint32_t htt_s = cvta_s(htt);
    const uint32_t att_s = cvta_s(attn_h);
    const uint32_t wtk_s = att_s;

    // ---------------- Prologue: a_s, adjacency bitmask, hs (fp16 h) -----------
    a_s[tid]       = ag[tid];
    a_s[256 + tid] = ag[256 + tid];

    #pragma unroll 8
    for (int it = 0; it < 64; it++) {
        int idx = it * 256 + tid;
        unsigned bal = __ballot_sync(0xffffffffu, adjb[idx] < ADJ_THR);
        if (lane == 0) maskb[idx >> 5] = bal;
    }

    // hs[row][k ^ 8*(row&7)] fp16
    #pragma unroll
    for (int it = 0; it < 8; it++) {
        int idx = it * 256 + tid;
        int row = idx >> 4;
        int k4  = (idx & 15) * 4;
        float4 v = *(const float4*)&hb[row * 64 + k4];
        __half* p = hs + row * 64 + (k4 ^ (8 * (row & 7)));
        *(half2*)p       = __floats2half2_rn(v.x, v.y);
        *(half2*)(p + 2) = __floats2half2_rn(v.z, v.w);
    }

    // GEMM2 accumulator: warp tile 32 rows x 32 cols, full K, all heads
    const int rblk = wid >> 1;      // row block (32 rows)
    const int chf  = wid & 1;       // col half (32 cols)
    float C[8][4];
    #pragma unroll
    for (int i = 0; i < 8; i++)
        #pragma unroll
        for (int q = 0; q < 4; q++) C[i][q] = 0.f;

    // ================== Per-head pipeline ==================
    #pragma unroll 1
    for (int h = 0; h < 4; h++) {
        __syncthreads();   // prev GEMM2 attn reads done (or prologue hs done)

        // ---- Stage Wtk[k][o ^ 8*(k&7)] = W[k][h*64+o] fp16 ----
        // Natural-direction stores: half2 along o, <=2-way conflicts.
        #pragma unroll
        for (int it = 0; it < 4; it++) {
            int idx = it * 256 + tid;
            int k   = idx >> 4;
            int o4  = (idx & 15) * 4;
            float4 v = *(const float4*)&Wg[k * 256 + h * 64 + o4];
            int base = k * 64 + (o4 ^ (8 * (k & 7)));
            *(half2*)&Wtk[base]     = __floats2half2_rn(v.x, v.y);
            *(half2*)&Wtk[base + 2] = __floats2half2_rn(v.z, v.w);
        }
        __syncthreads();

        // ---- GEMM1: htt[o][row] = W_h^T @ h^T ; warp tile 16 o x 64 rows ----
        // A fragments from Wtk via ldmatrix.trans ([k][o] storage).
        {
            const int ob = (wid >> 1) * 16;   // o block
            const int rb = wid & 1;           // row half (64 rows)
            const int krow = (lane & 7) + 8 * lhi;            // 0..15
            const int och  = ob + 8 * ((lane >> 3) & 1);
            const uint32_t aA_base =
                wtk_s + 2 * (krow * 64 + (och ^ (8 * (krow & 7))));
            const uint32_t aB0 = hs_s + 2 * ((rb * 64 + lrow) * 64);

            #pragma unroll
            for (int qh = 0; qh < 2; qh++) {
                float D[4][4];
                #pragma unroll
                for (int i = 0; i < 4; i++)
                    #pragma unroll
                    for (int q = 0; q < 4; q++) D[i][q] = 0.f;

                #pragma unroll
                for (int ks = 0; ks < 4; ks++) {
                    uint32_t A0, A1, A2, A3;
                    ldm_x4_t(A0, A1, A2, A3, aA_base + ks * 2048);
                    const int chunk = ((ks * 16 + 8 * lhi) ^ (8 * (lrow & 7))) * 2;
                    #pragma unroll
                    for (int q2 = 0; q2 < 2; q2++) {
                        const int q = qh * 2 + q2;
                        uint32_t r0, r1, r2, r3;
                        ldm_x4(r0, r1, r2, r3, aB0 + 2 * (q * 16 * 64) + chunk);
                        mma_f16(D[2 * q2],     A0, A1, A2, A3, r0, r2);
                        mma_f16(D[2 * q2 + 1], A0, A1, A2, A3, r1, r3);
                    }
                }
                // store htt (half2, conflict-free)
                #pragma unroll
                for (int q2 = 0; q2 < 2; q2++) {
                    #pragma unroll
                    for (int j = 0; j < 2; j++) {
                        const float* c = D[2 * q2 + j];
                        const int row = rb * 64 + (qh * 2 + q2) * 16 + j * 8 + 2 * t;
                        *(half2*)&htt[(ob + g) * HTS + row] =
                            __floats2half2_rn(c[0], c[1]);
                        *(half2*)&htt[(ob + g + 8) * HTS + row] =
                            __floats2half2_rn(c[2], c[3]);
                    }
                }
            }
        }
        __syncthreads();   // htt visible

        // ---- src/tgt: exact fp32 dots over htt columns (conflict-free) ----
        // lane = (ol = lane&7 -> o sub-index, rp = lane>>3 -> row pair)
        {
            const int ol = lane & 7;
            const int rp = lane >> 3;
            #pragma unroll
            for (int pass = 0; pass < 2; pass++) {
                const int row = wid * 16 + 2 * (rp + 4 * pass);
                float s0 = 0.f, s1 = 0.f, t0 = 0.f, t1 = 0.f;
                #pragma unroll
                for (int oo = 0; oo < 8; oo++) {
                    const int o = oo * 8 + ol;
                    float2 f = __half22float2(*(const half2*)&htt[o * HTS + row]);
                    float av = a_s[h * 128 + o];
                    float bv = a_s[h * 128 + 64 + o];
                    s0 = fmaf(f.x, av, s0); s1 = fmaf(f.y, av, s1);
                    t0 = fmaf(f.x, bv, t0); t1 = fmaf(f.y, bv, t1);
                }
                #pragma unroll
                for (int m = 1; m <= 4; m <<= 1) {
                    s0 += __shfl_xor_sync(0xffffffffu, s0, m);
                    s1 += __shfl_xor_sync(0xffffffffu, s1, m);
                    t0 += __shfl_xor_sync(0xffffffffu, t0, m);
                    t1 += __shfl_xor_sync(0xffffffffu, t1, m);
                }
                if (ol == 0) {
                    float2 sv; sv.x = s0; sv.y = s1;
                    float2 tv; tv.x = t0; tv.y = t1;
                    *(float2*)&src_s[row] = sv;
                    *(float2*)&tgt_s[row] = tv;
                }
            }
        }
        __syncthreads();   // src/tgt ready; Wtk dead -> attn region free

        // ---- e-phase: rows wid*16..+15; lane covers j=2L,2L+1 (+64) ----
        {
            float2 tA = *(const float2*)&tgt_s[2 * lane];
            float2 tB = *(const float2*)&tgt_s[64 + 2 * lane];
            const float tA0 = 0.5f * tA.x, tA1 = 0.5f * tA.y;
            const float tB0 = 0.5f * tB.x, tB1 = 0.5f * tB.y;
            const int mw = lane >> 4;
            const int mb = 2 * (lane & 15);

            #pragma unroll 2
            for (int rr = 0; rr < 16; rr++) {
                const int i = wid * 16 + rr;
                const float sih = 0.5f * src_s[i];
                unsigned w0 = maskb[i * 4 + mw]     >> mb;
                unsigned w1 = maskb[i * 4 + 2 + mw] >> mb;
                float p0 = exp_sigmoid_half(sih + tA0);
                float p1 = exp_sigmoid_half(sih + tA1);
                float p2 = exp_sigmoid_half(sih + tB0);
                float p3 = exp_sigmoid_half(sih + tB1);
                if (w0 & 1u) p0 = 0.f;
                if (w0 & 2u) p1 = 0.f;
                if (w1 & 1u) p2 = 0.f;
                if (w1 & 2u) p3 = 0.f;
                float rs = (p0 + p1) + (p2 + p3);
                #pragma unroll
                for (int m = 16; m >= 1; m >>= 1)
                    rs += __shfl_xor_sync(0xffffffffu, rs, m);
                const float inv = rcp_approx(rs);
                *(half2*)(attn_h + i * HTS + 2 * lane) =
                    __floats2half2_rn(p0 * inv, p1 * inv);
                *(half2*)(attn_h + i * HTS + 64 + 2 * lane) =
                    __floats2half2_rn(p2 * inv, p3 * inv);
            }
        }
        __syncthreads();

        // ---- GEMM2 (32x32 warp tile): C += attn[rblk*32.., ks] @ htt[chf*32.., ks] ----
        {
            const uint32_t aA0 = att_s + 2 * ((rblk * 32 + lrow) * HTS + 8 * lhi);
            const uint32_t aB0 = htt_s + 2 * ((chf * 32 + lrow) * HTS + 8 * lhi);

            #pragma unroll
            for (int ks = 0; ks < 8; ks++) {
                const uint32_t koff = 2 * (16 * ks);
                uint32_t A[2][4], B[2][4];
                ldm_x4(A[0][0], A[0][1], A[0][2], A[0][3], aA0 + koff);
                ldm_x4(A[1][0], A[1][1], A[1][2], A[1][3],
                       aA0 + 2 * (16 * HTS) + koff);
                ldm_x4(B[0][0], B[0][1], B[0][2], B[0][3], aB0 + koff);
                ldm_x4(B[1][0], B[1][1], B[1][2], B[1][3],
                       aB0 + 2 * (16 * HTS) + koff);
                #pragma unroll
                for (int mt = 0; mt < 2; mt++) {
                    mma_f16(C[mt * 4 + 0], A[mt][0], A[mt][1], A[mt][2], A[mt][3],
                            B[0][0], B[0][2]);
                    mma_f16(C[mt * 4 + 1], A[mt][0], A[mt][1], A[mt][2], A[mt][3],
                            B[0][1], B[0][3]);
                    mma_f16(C[mt * 4 + 2], A[mt][0], A[mt][1], A[mt][2], A[mt][3],
                            B[1][0], B[1][2]);
                    mma_f16(C[mt * 4 + 3], A[mt][0], A[mt][1], A[mt][2], A[mt][3],
                            B[1][1], B[1][3]);
                }
            }
        }
        // loop-top __syncthreads() protects attn before next Wtk stage
    }

    // ---------------- Epilogue: mean over heads -----
    #pragma unroll
    for (int mt = 0; mt < 2; mt++) {
        #pragma unroll
        for (int nt = 0; nt < 4; nt++) {
            const int ti  = mt * 4 + nt;
            const int row = rblk * 32 + mt * 16 + g;
            const int col = chf * 32 + nt * 8 + 2 * t;
            float2 o0; o0.x = C[ti][0] * 0.25f; o0.y = C[ti][1] * 0.25f;
            float2 o1; o1.x = C[ti][2] * 0.25f; o1.y = C[ti][3] * 0.25f;
            *(float2*)&outb[row * 64 + col]       = o0;
            *(float2*)&outb[(row + 8) * 64 + col] = o1;
        }
    }
}

extern "C" void kernel_launch(void* const* d_in, const int* in_sizes, int n_in,
                              void* d_out, int out_size)
{
    const float* h   = (const float*)d_in[0];
    const float* adj = (const float*)d_in[1];
    const float* W   = (const float*)d_in[2];
    const float* a   = (const float*)d_in[3];
    float* out = (float*)d_out;

    static bool attr_set = false;
    if (!attr_set) {
        cudaFuncSetAttribute(gat_fused_kernel,
                             cudaFuncAttributeMaxDynamicSharedMemorySize,
                             SMEM_BYTES);
        attr_set = true;
    }

    gat_fused_kernel<<<BATCH_SEQ, THREADS, SMEM_BYTES>>>(h, adj, W, a, out);
}

// round 14
// speedup vs baseline: 3.8188x; 1.0025x over previous
#include <cuda_runtime.h>
#include <cuda_fp16.h>
#include <cstdint>

// Problem constants
#define BATCH_SEQ 640          // B*S = 32*20
#define THREADS   256
#define ADJ_THR   0.05f
#define FULLC     444          // full-CTA count (= min co-resident slots @3/SM)
#define TAILB     (BATCH_SEQ - FULLC)   // 196 tail batch-seqs, 2 CTAs each

// K-split/head-pair partial buffer: 392 half-results of 128x64 f32
__device__ float g_scratch[2 * TAILB * 128 * 64];

__device__ __forceinline__ float rcp_approx(float x) {
    float r; asm("rcp.approx.f32 %0, %1;" : "=f"(r) : "f"(x)); return r;
}
__device__ __forceinline__ float tanh_apx(float x) {
    float r; asm("tanh.approx.f32 %0, %1;" : "=f"(r) : "f"(x)); return r;
}
__device__ __forceinline__ float ex2_apx(float x) {
    float r; asm("ex2.approx.f32 %0, %1;" : "=f"(r) : "f"(x)); return r;
}
// exp(sigmoid(x)) given xh = x/2:  exp(0.5*tanh(xh)+0.5) = 2^(c*tanh(xh)+c)
#define EXP_SIG_C 0.72134752044f   // log2(e)/2
__device__ __forceinline__ float exp_sigmoid_half(float xh) {
    return ex2_apx(fmaf(EXP_SIG_C, tanh_apx(xh), EXP_SIG_C));
}
// fp16 mma m16n8k16, fp32 accum
__device__ __forceinline__ void mma_f16(float c[4],
                                        uint32_t a0, uint32_t a1, uint32_t a2, uint32_t a3,
                                        uint32_t b0, uint32_t b1) {
    asm volatile("mma.sync.aligned.m16n8k16.row.col.f32.f16.f16.f32 "
                 "{%0,%1,%2,%3}, {%4,%5,%6,%7}, {%8,%9}, {%0,%1,%2,%3};"
                 : "+f"(c[0]), "+f"(c[1]), "+f"(c[2]), "+f"(c[3])
                 : "r"(a0), "r"(a1), "r"(a2), "r"(a3), "r"(b0), "r"(b1));
}
__device__ __forceinline__ uint32_t cvta_s(const void* p) {
    uint32_t a; asm("{ .reg .u64 t; cvta.to.shared.u64 t, %1; cvt.u32.u64 %0, t; }"
                    : "=r"(a) : "l"(p));
    return a;
}
__device__ __forceinline__ void ldm_x4(uint32_t& r0, uint32_t& r1,
                                       uint32_t& r2, uint32_t& r3, uint32_t a) {
    asm volatile("ldmatrix.sync.aligned.m8n8.x4.shared.b16 {%0,%1,%2,%3}, [%4];"
                 : "=r"(r0), "=r"(r1), "=r"(r2), "=r"(r3) : "r"(a));
}
__device__ __forceinline__ void ldm_x4_t(uint32_t& r0, uint32_t& r1,
                                         uint32_t& r2, uint32_t& r3, uint32_t a) {
    asm volatile("ldmatrix.sync.aligned.m8n8.x4.trans.shared.b16 {%0,%1,%2,%3}, [%4];"
                 : "=r"(r0), "=r"(r1), "=r"(r2), "=r"(r3) : "r"(a));
}

// Shared memory layout (bytes) — ONE head resident at a time:
//   hs   [128 row][64 k] fp16 XOR-swz @ 0      (16384)
//   htt  [64 o][136 k-halves] fp16    @ 16384  (17408)  current head's ht^T
//   ATT  @ 33792 (34816):
//     GEMM1 phase: Wtk [64 k][64 o] fp16, o XOR-swz by k  (8192)
//     attn phase : attn [128 i][136 k] fp16
//   src_s [128] f32  @ 68608 (512)
//   tgt_s [128] f32  @ 69120 (512)
//   maskb [512] u32  @ 69632 (2048)
//   a_s   [512] f32  @ 71680 (2048)
// total 73728 B -> 3 CTAs/SM
#define HTS       136
#define HTT_OFF   16384
#define ATT_OFF   33792
#define SRC_OFF   68608
#define TGT_OFF   69120
#define MSK_OFF   69632
#define AS_OFF    71680
#define SMEM_BYTES 73728

extern __shared__ char smem_b[];

__global__ __launch_bounds__(THREADS, 3)
void gat_fused_kernel(const float* __restrict__ hg,
                      const float* __restrict__ adjg,
                      const float* __restrict__ Wg,
                      const float* __restrict__ ag,
                      float* __restrict__ outg)
{
    __half* hs     = (__half*)smem_b;
    __half* htt    = (__half*)(smem_b + HTT_OFF);
    __half* attn_h = (__half*)(smem_b + ATT_OFF);
    __half* Wtk    = (__half*)(smem_b + ATT_OFF);   // union with attn
    float*  src_s  = (float*)(smem_b + SRC_OFF);
    float*  tgt_s  = (float*)(smem_b + TGT_OFF);
    unsigned* maskb = (unsigned*)(smem_b + MSK_OFF);
    float*  a_s    = (float*)(smem_b + AS_OFF);

    const int tid  = threadIdx.x;
    const int lane = tid & 31;
    const int wid  = tid >> 5;      // 0..7
    const int g    = lane >> 2;     // 0..7
    const int t    = lane & 3;      // 0..3
    const int lrow = lane & 15;
    const int lhi  = lane >> 4;
    const int bid  = blockIdx.x;

    // ---- Mixed-grid decode: full CTA (4 heads) or tail CTA (head pair) ----
    int bs, h0, h1;
    float* obase;
    if (bid < FULLC) {
        bs = bid; h0 = 0; h1 = 4;
        obase = outg + (size_t)bs * 128 * 64;
    } else {
        int r  = bid - FULLC;
        bs = FULLC + (r >> 1);
        h0 = (r & 1) * 2; h1 = h0 + 2;
        obase = g_scratch + (size_t)r * 128 * 64;
    }

    const float* hb   = hg   + (size_t)bs * 128 * 64;
    const float* adjb = adjg + (size_t)bs * 128 * 128;

    const uint32_t hs_s  = cvta_s(hs);
    const uint32_t htt_s = cvta_s(htt);
    const uint32_t att_s = cvta_s(attn_h);
    const uint32_t wtk_s = att_s;

    // ---------------- Prologue: a_s, adjacency bitmask, hs (fp16 h) -----------
    a_s[tid]       = ag[tid];
    a_s[256 + tid] = ag[256 + tid];

    #pragma unroll 8
    for (int it = 0; it < 64; it++) {
        int idx = it * 256 + tid;
        unsigned bal = __ballot_sync(0xffffffffu, adjb[idx] < ADJ_THR);
        if (lane == 0) maskb[idx >> 5] = bal;
    }

    // hs[row][k ^ 8*(row&7)] fp16
    #pragma unroll
    for (int it = 0; it < 8; it++) {
        int idx = it * 256 + tid;
        int row = idx >> 4;
        int k4  = (idx & 15) * 4;
        float4 v = *(const float4*)&hb[row * 64 + k4];
        __half* p = hs + row * 64 + (k4 ^ (8 * (row & 7)));
        *(half2*)p       = __floats2half2_rn(v.x, v.y);
        *(half2*)(p + 2) = __floats2half2_rn(v.z, v.w);
    }

    // GEMM2 accumulator: warp tile 32 rows x 32 cols, full K, heads h0..h1
    const int rblk = wid >> 1;      // row block (32 rows)
    const int chf  = wid & 1;       // col half (32 cols)
    float C[8][4];
    #pragma unroll
    for (int i = 0; i < 8; i++)
        #pragma unroll
        for (int q = 0; q < 4; q++) C[i][q] = 0.f;

    // ================== Per-head pipeline ==================
    #pragma unroll 1
    for (int h = h0; h < h1; h++) {
        __syncthreads();   // prev GEMM2 attn reads done (or prologue hs done)

        // ---- Stage Wtk[k][o ^ 8*(k&7)] = W[k][h*64+o] fp16 ----
        #pragma unroll
        for (int it = 0; it < 4; it++) {
            int idx = it * 256 + tid;
            int k   = idx >> 4;
            int o4  = (idx & 15) * 4;
            float4 v = *(const float4*)&Wg[k * 256 + h * 64 + o4];
            int base = k * 64 + (o4 ^ (8 * (k & 7)));
            *(half2*)&Wtk[base]     = __floats2half2_rn(v.x, v.y);
            *(half2*)&Wtk[base + 2] = __floats2half2_rn(v.z, v.w);
        }
        __syncthreads();

        // ---- GEMM1: htt[o][row] = W_h^T @ h^T ; warp tile 16 o x 64 rows ----
        {
            const int ob = (wid >> 1) * 16;   // o block
            const int rb = wid & 1;           // row half (64 rows)
            const int krow = (lane & 7) + 8 * lhi;            // 0..15
            const int och  = ob + 8 * ((lane >> 3) & 1);
            const uint32_t aA_base =
                wtk_s + 2 * (krow * 64 + (och ^ (8 * (krow & 7))));
            const uint32_t aB0 = hs_s + 2 * ((rb * 64 + lrow) * 64);

            #pragma unroll
            for (int qh = 0; qh < 2; qh++) {
                float D[4][4];
                #pragma unroll
                for (int i = 0; i < 4; i++)
                    #pragma unroll
                    for (int q = 0; q < 4; q++) D[i][q] = 0.f;

                #pragma unroll
                for (int ks = 0; ks < 4; ks++) {
                    uint32_t A0, A1, A2, A3;
                    ldm_x4_t(A0, A1, A2, A3, aA_base + ks * 2048);
                    const int chunk = ((ks * 16 + 8 * lhi) ^ (8 * (lrow & 7))) * 2;
                    #pragma unroll
                    for (int q2 = 0; q2 < 2; q2++) {
                        const int q = qh * 2 + q2;
                        uint32_t r0, r1, r2, r3;
                        ldm_x4(r0, r1, r2, r3, aB0 + 2 * (q * 16 * 64) + chunk);
                        mma_f16(D[2 * q2],     A0, A1, A2, A3, r0, r2);
                        mma_f16(D[2 * q2 + 1], A0, A1, A2, A3, r1, r3);
                    }
                }
                // store htt (half2, conflict-free)
                #pragma unroll
                for (int q2 = 0; q2 < 2; q2++) {
                    #pragma unroll
                    for (int j = 0; j < 2; j++) {
                        const float* c = D[2 * q2 + j];
                        const int row = rb * 64 + (qh * 2 + q2) * 16 + j * 8 + 2 * t;
                        *(half2*)&htt[(ob + g) * HTS + row] =
                            __floats2half2_rn(c[0], c[1]);
                        *(half2*)&htt[(ob + g + 8) * HTS + row] =
                            __floats2half2_rn(c[2], c[3]);
                    }
                }
            }
        }
        __syncthreads();   // htt visible

        // ---- src/tgt: exact fp32 dots over htt columns (conflict-free) ----
        {
            const int ol = lane & 7;
            const int rp = lane >> 3;
            #pragma unroll
            for (int pass = 0; pass < 2; pass++) {
                const int row = wid * 16 + 2 * (rp + 4 * pass);
                float s0 = 0.f, s1 = 0.f, t0 = 0.f, t1 = 0.f;
                #pragma unroll
                for (int oo = 0; oo < 8; oo++) {
                    const int o = oo * 8 + ol;
                    float2 f = __half22float2(*(const half2*)&htt[o * HTS + row]);
                    float av = a_s[h * 128 + o];
                    float bv = a_s[h * 128 + 64 + o];
                    s0 = fmaf(f.x, av, s0); s1 = fmaf(f.y, av, s1);
                    t0 = fmaf(f.x, bv, t0); t1 = fmaf(f.y, bv, t1);
                }
                #pragma unroll
                for (int m = 1; m <= 4; m <<= 1) {
                    s0 += __shfl_xor_sync(0xffffffffu, s0, m);
                    s1 += __shfl_xor_sync(0xffffffffu, s1, m);
                    t0 += __shfl_xor_sync(0xffffffffu, t0, m);
                    t1 += __shfl_xor_sync(0xffffffffu, t1, m);
                }
                if (ol == 0) {
                    float2 sv; sv.x = s0; sv.y = s1;
                    float2 tv; tv.x = t0; tv.y = t1;
                    *(float2*)&src_s[row] = sv;
                    *(float2*)&tgt_s[row] = tv;
                }
            }
        }
        __syncthreads();   // src/tgt ready; Wtk dead -> attn region free

        // ---- e-phase: rows wid*16..+15; lane covers j=2L,2L+1 (+64) ----
        {
            float2 tA = *(const float2*)&tgt_s[2 * lane];
            float2 tB = *(const float2*)&tgt_s[64 + 2 * lane];
            const float tA0 = 0.5f * tA.x, tA1 = 0.5f * tA.y;
            const float tB0 = 0.5f * tB.x, tB1 = 0.5f * tB.y;
            const int mw = lane >> 4;
            const int mb = 2 * (lane & 15);

            #pragma unroll 2
            for (int rr = 0; rr < 16; rr++) {
                const int i = wid * 16 + rr;
                const float sih = 0.5f * src_s[i];
                unsigned w0 = maskb[i * 4 + mw]     >> mb;
                unsigned w1 = maskb[i * 4 + 2 + mw] >> mb;
                float p0 = exp_sigmoid_half(sih + tA0);
                float p1 = exp_sigmoid_half(sih + tA1);
                float p2 = exp_sigmoid_half(sih + tB0);
                float p3 = exp_sigmoid_half(sih + tB1);
                if (w0 & 1u) p0 = 0.f;
                if (w0 & 2u) p1 = 0.f;
                if (w1 & 1u) p2 = 0.f;
                if (w1 & 2u) p3 = 0.f;
                float rs = (p0 + p1) + (p2 + p3);
                #pragma unroll
                for (int m = 16; m >= 1; m >>= 1)
                    rs += __shfl_xor_sync(0xffffffffu, rs, m);
                const float inv = rcp_approx(rs);
                *(half2*)(attn_h + i * HTS + 2 * lane) =
                    __floats2half2_rn(p0 * inv, p1 * inv);
                *(half2*)(attn_h + i * HTS + 64 + 2 * lane) =
                    __floats2half2_rn(p2 * inv, p3 * inv);
            }
        }
        __syncthreads();

        // ---- GEMM2 (32x32 warp tile): C += attn[rblk*32.., :] @ htt[chf*32.., :] ----
        {
            const uint32_t aA0 = att_s + 2 * ((rblk * 32 + lrow) * HTS + 8 * lhi);
            const uint32_t aB0 = htt_s + 2 * ((chf * 32 + lrow) * HTS + 8 * lhi);

            #pragma unroll
            for (int ks = 0; ks < 8; ks++) {
                const uint32_t koff = 2 * (16 * ks);
                uint32_t A[2][4], B[2][4];
                ldm_x4(A[0][0], A[0][1], A[0][2], A[0][3], aA0 + koff);
                ldm_x4(A[1][0], A[1][1], A[1][2], A[1][3],
                       aA0 + 2 * (16 * HTS) + koff);
                ldm_x4(B[0][0], B[0][1], B[0][2], B[0][3], aB0 + koff);
                ldm_x4(B[1][0], B[1][1], B[1][2], B[1][3],
                       aB0 + 2 * (16 * HTS) + koff);
                #pragma unroll
                for (int mt = 0; mt < 2; mt++) {
                    mma_f16(C[mt * 4 + 0], A[mt][0], A[mt][1], A[mt][2], A[mt][3],
                            B[0][0], B[0][2]);
                    mma_f16(C[mt * 4 + 1], A[mt][0], A[mt][1], A[mt][2], A[mt][3],
                            B[0][1], B[0][3]);
                    mma_f16(C[mt * 4 + 2], A[mt][0], A[mt][1], A[mt][2], A[mt][3],
                            B[1][0], B[1][2]);
                    mma_f16(C[mt * 4 + 3], A[mt][0], A[mt][1], A[mt][2], A[mt][3],
                            B[1][1], B[1][3]);
                }
            }
        }
        // loop-top __syncthreads() protects attn before next Wtk stage
    }

    // ---------------- Epilogue: x0.25, to out (full) or scratch (tail) -----
    #pragma unroll
    for (int mt = 0; mt < 2; mt++) {
        #pragma unroll
        for (int nt = 0; nt < 4; nt++) {
            const int ti  = mt * 4 + nt;
            const int row = rblk * 32 + mt * 16 + g;
            const int col = chf * 32 + nt * 8 + 2 * t;
            float2 o0; o0.x = C[ti][0] * 0.25f; o0.y = C[ti][1] * 0.25f;
            float2 o1; o1.x = C[ti][2] * 0.25f; o1.y = C[ti][3] * 0.25f;
            *(float2*)&obase[row * 64 + col]       = o0;
            *(float2*)&obase[(row + 8) * 64 + col] = o1;
        }
    }
}

// Combine the two head-pair partials for each tail batch-seq.
__global__ __launch_bounds__(256)
void gat_combine_kernel(float* __restrict__ outg)
{
    const int p   = blockIdx.x;          // 0..TAILB-1
    const int tid = threadIdx.x;
    const float4* a = (const float4*)(g_scratch + (size_t)(2 * p) * 8192);
    const float4* b = (const float4*)(g_scratch + (size_t)(2 * p + 1) * 8192);
    float4* o = (float4*)(outg + (size_t)(FULLC + p) * 8192);
    #pragma unroll
    for (int i = 0; i < 8; i++) {
        int idx = i * 256 + tid;
        float4 x = a[idx], y = b[idx];
        x.x += y.x; x.y += y.y; x.z += y.z; x.w += y.w;
        o[idx] = x;
    }
}

extern "C" void kernel_launch(void* const* d_in, const int* in_sizes, int n_in,
                              void* d_out, int out_size)
{
    const float* h   = (const float*)d_in[0];
    const float* adj = (const float*)d_in[1];
    const float* W   = (const float*)d_in[2];
    const float* a   = (const float*)d_in[3];
    float* out = (float*)d_out;

    static bool attr_set = false;
    if (!attr_set) {
        cudaFuncSetAttribute(gat_fused_kernel,
                             cudaFuncAttributeMaxDynamicSharedMemorySize,
                             SMEM_BYTES);
        attr_set = true;
    }

    gat_fused_kernel<<<FULLC + 2 * TAILB, THREADS, SMEM_BYTES>>>(h, adj, W, a, out);
    gat_combine_kernel<<<TAILB, 256>>>(out);
}

// round 15
// speedup vs baseline: 4.1514x; 1.0871x over previous
#include <cuda_runtime.h>
#include <cuda_fp16.h>
#include <cstdint>
#include <cstring>

// Problem constants
#define BATCH_SEQ 640          // B*S = 32*20
#define THREADS   256
#define ADJ_THR   0.05f
#define FULLC     444          // full-CTA count (= min co-resident slots @3/SM)
#define TAILB     (BATCH_SEQ - FULLC)   // 196 tail batch-seqs, 2 CTAs each

__device__ __forceinline__ float rcp_approx(float x) {
    float r; asm("rcp.approx.f32 %0, %1;" : "=f"(r) : "f"(x)); return r;
}
__device__ __forceinline__ uint32_t h2u(half2 v) { uint32_t r; memcpy(&r, &v, 4); return r; }
__device__ __forceinline__ half2 u2h(uint32_t v) { half2 r; memcpy(&r, &v, 4); return r; }
// exp(sigmoid(x)) pairwise in fp16: 2^(c*tanh(x/2)+c), c = log2(e)/2
#define EXP_SIG_C 0.72134752044f
// fp16 mma m16n8k16, fp32 accum
__device__ __forceinline__ void mma_f16(float c[4],
                                        uint32_t a0, uint32_t a1, uint32_t a2, uint32_t a3,
                                        uint32_t b0, uint32_t b1) {
    asm volatile("mma.sync.aligned.m16n8k16.row.col.f32.f16.f16.f32 "
                 "{%0,%1,%2,%3}, {%4,%5,%6,%7}, {%8,%9}, {%0,%1,%2,%3};"
                 : "+f"(c[0]), "+f"(c[1]), "+f"(c[2]), "+f"(c[3])
                 : "r"(a0), "r"(a1), "r"(a2), "r"(a3), "r"(b0), "r"(b1));
}
__device__ __forceinline__ uint32_t cvta_s(const void* p) {
    uint32_t a; asm("{ .reg .u64 t; cvta.to.shared.u64 t, %1; cvt.u32.u64 %0, t; }"
                    : "=r"(a) : "l"(p));
    return a;
}
__device__ __forceinline__ void ldm_x4(uint32_t& r0, uint32_t& r1,
                                       uint32_t& r2, uint32_t& r3, uint32_t a) {
    asm volatile("ldmatrix.sync.aligned.m8n8.x4.shared.b16 {%0,%1,%2,%3}, [%4];"
                 : "=r"(r0), "=r"(r1), "=r"(r2), "=r"(r3) : "r"(a));
}
__device__ __forceinline__ void ldm_x4_t(uint32_t& r0, uint32_t& r1,
                                         uint32_t& r2, uint32_t& r3, uint32_t a) {
    asm volatile("ldmatrix.sync.aligned.m8n8.x4.trans.shared.b16 {%0,%1,%2,%3}, [%4];"
                 : "=r"(r0), "=r"(r1), "=r"(r2), "=r"(r3) : "r"(a));
}
__device__ __forceinline__ void red_add_f32(float* p, float v) {
    asm volatile("red.global.add.f32 [%0], %1;" :: "l"(p), "f"(v) : "memory");
}

// Shared memory layout (bytes) — ONE head resident at a time:
//   hs   [128 row][64 k] fp16 XOR-swz @ 0      (16384)
//   htt  [64 o][136 k-halves] fp16    @ 16384  (17408)  current head's ht^T
//   ATT  @ 33792 (34816):
//     GEMM1 phase: Wtk [64 k][64 o] fp16, o XOR-swz by k  (8192)
//     attn phase : attn [128 i][136 k] fp16
//   src_s [128] f32  @ 68608 (512)
//   tgt_s [128] f32  @ 69120 (512)
//   maskb [512] u32  @ 69632 (2048)
//   a_s   [512] f32  @ 71680 (2048)
// total 73728 B -> 3 CTAs/SM
#define HTS       136
#define HTT_OFF   16384
#define ATT_OFF   33792
#define SRC_OFF   68608
#define TGT_OFF   69120
#define MSK_OFF   69632
#define AS_OFF    71680
#define SMEM_BYTES 73728

extern __shared__ char smem_b[];

__global__ __launch_bounds__(THREADS, 3)
void gat_fused_kernel(const float* __restrict__ hg,
                      const float* __restrict__ adjg,
                      const float* __restrict__ Wg,
                      const float* __restrict__ ag,
                      float* __restrict__ outg)
{
    __half* hs     = (__half*)smem_b;
    __half* htt    = (__half*)(smem_b + HTT_OFF);
    __half* attn_h = (__half*)(smem_b + ATT_OFF);
    __half* Wtk    = (__half*)(smem_b + ATT_OFF);   // union with attn
    float*  src_s  = (float*)(smem_b + SRC_OFF);
    float*  tgt_s  = (float*)(smem_b + TGT_OFF);
    unsigned* maskb = (unsigned*)(smem_b + MSK_OFF);
    float*  a_s    = (float*)(smem_b + AS_OFF);

    const int tid  = threadIdx.x;
    const int lane = tid & 31;
    const int wid  = tid >> 5;      // 0..7
    const int g    = lane >> 2;     // 0..7
    const int t    = lane & 3;      // 0..3
    const int lrow = lane & 15;
    const int lhi  = lane >> 4;
    const int bid  = blockIdx.x;

    // ---- Mixed-grid decode: full CTA (4 heads) or tail CTA (head pair) ----
    int bs, h0, h1;
    bool full;
    if (bid < FULLC) {
        bs = bid; h0 = 0; h1 = 4; full = true;
    } else {
        int r  = bid - FULLC;
        bs = FULLC + (r >> 1);
        h0 = (r & 1) * 2; h1 = h0 + 2; full = false;
    }
    float* obase = outg + (size_t)bs * 128 * 64;

    const float* hb   = hg   + (size_t)bs * 128 * 64;
    const float* adjb = adjg + (size_t)bs * 128 * 128;

    const uint32_t hs_s  = cvta_s(hs);
    const uint32_t htt_s = cvta_s(htt);
    const uint32_t att_s = cvta_s(attn_h);
    const uint32_t wtk_s = att_s;

    // ---------------- Prologue: a_s, adjacency bitmask, hs (fp16 h) -----------
    a_s[tid]       = ag[tid];
    a_s[256 + tid] = ag[256 + tid];

    #pragma unroll 8
    for (int it = 0; it < 64; it++) {
        int idx = it * 256 + tid;
        unsigned bal = __ballot_sync(0xffffffffu, adjb[idx] < ADJ_THR);
        if (lane == 0) maskb[idx >> 5] = bal;
    }

    // hs[row][k ^ 8*(row&7)] fp16
    #pragma unroll
    for (int it = 0; it < 8; it++) {
        int idx = it * 256 + tid;
        int row = idx >> 4;
        int k4  = (idx & 15) * 4;
        float4 v = *(const float4*)&hb[row * 64 + k4];
        __half* p = hs + row * 64 + (k4 ^ (8 * (row & 7)));
        *(half2*)p       = __floats2half2_rn(v.x, v.y);
        *(half2*)(p + 2) = __floats2half2_rn(v.z, v.w);
    }

    // GEMM2 accumulator: warp tile 32 rows x 32 cols, full K, heads h0..h1
    const int rblk = wid >> 1;      // row block (32 rows)
    const int chf  = wid & 1;       // col half (32 cols)
    float C[8][4];
    #pragma unroll
    for (int i = 0; i < 8; i++)
        #pragma unroll
        for (int q = 0; q < 4; q++) C[i][q] = 0.f;

    // ================== Per-head pipeline ==================
    #pragma unroll 1
    for (int h = h0; h < h1; h++) {
        __syncthreads();   // prev GEMM2 attn reads done (or prologue hs done)

        // ---- Stage Wtk[k][o ^ 8*(k&7)] = W[k][h*64+o] fp16 ----
        #pragma unroll
        for (int it = 0; it < 4; it++) {
            int idx = it * 256 + tid;
            int k   = idx >> 4;
            int o4  = (idx & 15) * 4;
            float4 v = *(const float4*)&Wg[k * 256 + h * 64 + o4];
            int base = k * 64 + (o4 ^ (8 * (k & 7)));
            *(half2*)&Wtk[base]     = __floats2half2_rn(v.x, v.y);
            *(half2*)&Wtk[base + 2] = __floats2half2_rn(v.z, v.w);
        }
        __syncthreads();

        // ---- GEMM1: htt[o][row] = W_h^T @ h^T ; warp tile 16 o x 64 rows ----
        {
            const int ob = (wid >> 1) * 16;   // o block
            const int rb = wid & 1;           // row half (64 rows)
            const int krow = (lane & 7) + 8 * lhi;            // 0..15
            const int och  = ob + 8 * ((lane >> 3) & 1);
            const uint32_t aA_base =
                wtk_s + 2 * (krow * 64 + (och ^ (8 * (krow & 7))));
            const uint32_t aB0 = hs_s + 2 * ((rb * 64 + lrow) * 64);

            #pragma unroll
            for (int qh = 0; qh < 2; qh++) {
                float D[4][4];
                #pragma unroll
                for (int i = 0; i < 4; i++)
                    #pragma unroll
                    for (int q = 0; q < 4; q++) D[i][q] = 0.f;

                #pragma unroll
                for (int ks = 0; ks < 4; ks++) {
                    uint32_t A0, A1, A2, A3;
                    ldm_x4_t(A0, A1, A2, A3, aA_base + ks * 2048);
                    const int chunk = ((ks * 16 + 8 * lhi) ^ (8 * (lrow & 7))) * 2;
                    #pragma unroll
                    for (int q2 = 0; q2 < 2; q2++) {
                        const int q = qh * 2 + q2;
                        uint32_t r0, r1, r2, r3;
                        ldm_x4(r0, r1, r2, r3, aB0 + 2 * (q * 16 * 64) + chunk);
                        mma_f16(D[2 * q2],     A0, A1, A2, A3, r0, r2);
                        mma_f16(D[2 * q2 + 1], A0, A1, A2, A3, r1, r3);
                    }
                }
                // store htt (half2, conflict-free)
                #pragma unroll
                for (int q2 = 0; q2 < 2; q2++) {
                    #pragma unroll
                    for (int j = 0; j < 2; j++) {
                        const float* c = D[2 * q2 + j];
                        const int row = rb * 64 + (qh * 2 + q2) * 16 + j * 8 + 2 * t;
                        *(half2*)&htt[(ob + g) * HTS + row] =
                            __floats2half2_rn(c[0], c[1]);
                        *(half2*)&htt[(ob + g + 8) * HTS + row] =
                            __floats2half2_rn(c[2], c[3]);
                    }
                }
            }
        }
        __syncthreads();   // htt visible

        // ---- src/tgt: exact fp32 dots over htt columns (conflict-free) ----
        {
            const int ol = lane & 7;
            const int rp = lane >> 3;
            #pragma unroll
            for (int pass = 0; pass < 2; pass++) {
                const int row = wid * 16 + 2 * (rp + 4 * pass);
                float s0 = 0.f, s1 = 0.f, t0 = 0.f, t1 = 0.f;
                #pragma unroll
                for (int oo = 0; oo < 8; oo++) {
                    const int o = oo * 8 + ol;
                    float2 f = __half22float2(*(const half2*)&htt[o * HTS + row]);
                    float av = a_s[h * 128 + o];
                    float bv = a_s[h * 128 + 64 + o];
                    s0 = fmaf(f.x, av, s0); s1 = fmaf(f.y, av, s1);
                    t0 = fmaf(f.x, bv, t0); t1 = fmaf(f.y, bv, t1);
                }
                #pragma unroll
                for (int m = 1; m <= 4; m <<= 1) {
                    s0 += __shfl_xor_sync(0xffffffffu, s0, m);
                    s1 += __shfl_xor_sync(0xffffffffu, s1, m);
                    t0 += __shfl_xor_sync(0xffffffffu, t0, m);
                    t1 += __shfl_xor_sync(0xffffffffu, t1, m);
                }
                if (ol == 0) {
                    float2 sv; sv.x = s0; sv.y = s1;
                    float2 tv; tv.x = t0; tv.y = t1;
                    *(float2*)&src_s[row] = sv;
                    *(float2*)&tgt_s[row] = tv;
                }
            }
        }
        __syncthreads();   // src/tgt ready; Wtk dead -> attn region free

        // ---- e-phase (fp16x2 MUFU): rows wid*16..+15; lane j=2L,2L+1 (+64) ----
        {
            float2 tAf = *(const float2*)&tgt_s[2 * lane];
            float2 tBf = *(const float2*)&tgt_s[64 + 2 * lane];
            const half2 tA2 = __floats2half2_rn(0.5f * tAf.x, 0.5f * tAf.y);
            const half2 tB2 = __floats2half2_rn(0.5f * tBf.x, 0.5f * tBf.y);
            const half2 c2  = __float2half2_rn(EXP_SIG_C);
            const int mw = lane >> 4;
            const int mb = 2 * (lane & 15);

            #pragma unroll 2
            for (int rr = 0; rr < 16; rr++) {
                const int i = wid * 16 + rr;
                const half2 si2 = __float2half2_rn(0.5f * src_s[i]);
                unsigned w0 = maskb[i * 4 + mw]     >> mb;
                unsigned w1 = maskb[i * 4 + 2 + mw] >> mb;
                uint32_t thA, thB, pAb, pBb;
                asm("tanh.approx.f16x2 %0, %1;" : "=r"(thA) : "r"(h2u(__hadd2(si2, tA2))));
                asm("tanh.approx.f16x2 %0, %1;" : "=r"(thB) : "r"(h2u(__hadd2(si2, tB2))));
                asm("ex2.approx.f16x2 %0, %1;"
                    : "=r"(pAb) : "r"(h2u(__hfma2(c2, u2h(thA), c2))));
                asm("ex2.approx.f16x2 %0, %1;"
                    : "=r"(pBb) : "r"(h2u(__hfma2(c2, u2h(thB), c2))));
                uint32_t mA = ((w0 & 1u) ? 0u : 0xFFFFu) | ((w0 & 2u) ? 0u : 0xFFFF0000u);
                uint32_t mB = ((w1 & 1u) ? 0u : 0xFFFFu) | ((w1 & 2u) ? 0u : 0xFFFF0000u);
                half2 pa = u2h(pAb & mA);
                half2 pb = u2h(pBb & mB);
                float2 sf = __half22float2(__hadd2(pa, pb));
                float rs = sf.x + sf.y;
                #pragma unroll
                for (int m = 16; m >= 1; m >>= 1)
                    rs += __shfl_xor_sync(0xffffffffu, rs, m);
                const half2 inv2 = __float2half2_rn(rcp_approx(rs));
                *(half2*)(attn_h + i * HTS + 2 * lane)      = __hmul2(pa, inv2);
                *(half2*)(attn_h + i * HTS + 64 + 2 * lane) = __hmul2(pb, inv2);
            }
        }
        __syncthreads();

        // ---- GEMM2 (32x32 warp tile): C += attn[rblk*32.., :] @ htt[chf*32.., :] ----
        {
            const uint32_t aA0 = att_s + 2 * ((rblk * 32 + lrow) * HTS + 8 * lhi);
            const uint32_t aB0 = htt_s + 2 * ((chf * 32 + lrow) * HTS + 8 * lhi);

            #pragma unroll
            for (int ks = 0; ks < 8; ks++) {
                const uint32_t koff = 2 * (16 * ks);
                uint32_t A[2][4], B[2][4];
                ldm_x4(A[0][0], A[0][1], A[0][2], A[0][3], aA0 + koff);
                ldm_x4(A[1][0], A[1][1], A[1][2], A[1][3],
                       aA0 + 2 * (16 * HTS) + koff);
                ldm_x4(B[0][0], B[0][1], B[0][2], B[0][3], aB0 + koff);
                ldm_x4(B[1][0], B[1][1], B[1][2], B[1][3],
                       aB0 + 2 * (16 * HTS) + koff);
                #pragma unroll
                for (int mt = 0; mt < 2; mt++) {
                    mma_f16(C[mt * 4 + 0], A[mt][0], A[mt][1], A[mt][2], A[mt][3],
                            B[0][0], B[0][2]);
                    mma_f16(C[mt * 4 + 1], A[mt][0], A[mt][1], A[mt][2], A[mt][3],
                            B[0][1], B[0][3]);
                    mma_f16(C[mt * 4 + 2], A[mt][0], A[mt][1], A[mt][2], A[mt][3],
                            B[1][0], B[1][2]);
                    mma_f16(C[mt * 4 + 3], A[mt][0], A[mt][1], A[mt][2], A[mt][3],
                            B[1][1], B[1][3]);
                }
            }
        }
        // loop-top __syncthreads() protects attn before next Wtk stage
    }

    // ---------------- Epilogue: x0.25 -> out (full: store; tail: red.add) -----
    #pragma unroll
    for (int mt = 0; mt < 2; mt++) {
        #pragma unroll
        for (int nt = 0; nt < 4; nt++) {
            const int ti  = mt * 4 + nt;
            const int row = rblk * 32 + mt * 16 + g;
            const int col = chf * 32 + nt * 8 + 2 * t;
            float v0 = C[ti][0] * 0.25f, v1 = C[ti][1] * 0.25f;
            float v2 = C[ti][2] * 0.25f, v3 = C[ti][3] * 0.25f;
            if (full) {
                float2 o0; o0.x = v0; o0.y = v1;
                float2 o1; o1.x = v2; o1.y = v3;
                *(float2*)&obase[row * 64 + col]       = o0;
                *(float2*)&obase[(row + 8) * 64 + col] = o1;
            } else {
                // two commutative adds onto zeroed memory -> deterministic
                red_add_f32(&obase[row * 64 + col],           v0);
                red_add_f32(&obase[row * 64 + col + 1],       v1);
                red_add_f32(&obase[(row + 8) * 64 + col],     v2);
                red_add_f32(&obase[(row + 8) * 64 + col + 1], v3);
            }
        }
    }
}

extern "C" void kernel_launch(void* const* d_in, const int* in_sizes, int n_in,
                              void* d_out, int out_size)
{
    const float* h   = (const float*)d_in[0];
    const float* adj = (const float*)d_in[1];
    const float* W   = (const float*)d_in[2];
    const float* a   = (const float*)d_in[3];
    float* out = (float*)d_out;

    static bool attr_set = false;
    if (!attr_set) {
        cudaFuncSetAttribute(gat_fused_kernel,
                             cudaFuncAttributeMaxDynamicSharedMemorySize,
                             SMEM_BYTES);
        attr_set = true;
    }

    // Zero the tail region (accumulated via red.global.add by tail CTAs).
    cudaMemsetAsync(out + (size_t)FULLC * 128 * 64, 0,
                    (size_t)TAILB * 128 * 64 * sizeof(float), 0);
    gat_fused_kernel<<<FULLC + 2 * TAILB, THREADS, SMEM_BYTES>>>(h, adj, W, a, out);
}